// round 9
// baseline (speedup 1.0000x reference)
#include <cuda_runtime.h>
#include <math.h>
#include <stdint.h>

#define PL 512
#define EL 128
#define SS 640
#define TH 960
#define EH 720
#define EHP 736              /* EH row-padded for bulk A reads */
#define TI 2560
#define EI 2048
#define NH 15
#define NKV 5
#define HD 64
#define LAYERS 16

// ---------------- activation scratch (device globals, zero-init) ----------
__device__ __align__(256) float g_vlm[PL * TH];
__device__ __align__(256) float g_exp[EL * EH];
__device__ __align__(256) float g_hv [PL * TH];
__device__ __align__(256) float g_he [EL * EHP];   // cols [720,736) stay 0
__device__ __align__(256) float g_q  [SS * NH * HD];
__device__ __align__(256) float g_k  [SS * NKV * HD];
__device__ __align__(256) float g_v  [SS * NKV * HD];
__device__ __align__(256) float g_ke [PL * NKV * HD];
__device__ __align__(256) float g_ve [PL * NKV * HD];
__device__ __align__(256) float g_att[SS * NH * HD];
__device__ __align__(256) float g_g  [PL * TI];
__device__ __align__(256) float g_u  [PL * TI];
__device__ __align__(256) float g_ge [EL * EI];
__device__ __align__(256) float g_ue [EL * EI];

// ================= bulk-copy pipelined TF32 GEMM =================
// C[M,N] = (ACCUM? C:0) + A[M,K] @ B[K,N], fp32 in/out, tf32 mma (in-kernel
// cvt.rna on both operands — numerics identical to round-4 kernel).
// Block 128x64, BK=32, 256 threads = 8 warps (warp tile 32x32),
// 3-stage cp.async.bulk ring, per-stage mbarrier expect_tx.
// Requirements: M%128==0; lda >= ceil(K,32)*32; B rows beyond K are zeroed
// in smem (never read OOB); partial N tiles use narrowed bulk width.
#define GBK 32
#define ASTRIDE 36
#define BSTRIDE 72
#define SA (128 * ASTRIDE)          // 4608 floats
#define SB (GBK * BSTRIDE)          // 2304 floats
#define STAGEF (SA + SB)
#define STAGES 3
#define GEMM_SMEM (STAGES * STAGEF * 4)   // 82944 bytes

struct GemmSeg { const float* A; int lda; const float* B; float* C; int N; int tiles; };
struct GemmSegs { GemmSeg s[3]; };

__device__ __forceinline__ uint32_t f2tf32(float x) {
    uint32_t r;
    asm("cvt.rna.tf32.f32 %0, %1;" : "=r"(r) : "f"(x));
    return r;
}
__device__ __forceinline__ void mbar_init(uint32_t mb, uint32_t cnt) {
    asm volatile("mbarrier.init.shared.b64 [%0], %1;" :: "r"(mb), "r"(cnt) : "memory");
}
__device__ __forceinline__ void mbar_expect(uint32_t mb, uint32_t bytes) {
    asm volatile("mbarrier.arrive.expect_tx.shared.b64 _, [%0], %1;"
                 :: "r"(mb), "r"(bytes) : "memory");
}
__device__ __forceinline__ void bulk_g2s(uint32_t dst, const float* src,
                                         uint32_t bytes, uint32_t mb) {
    asm volatile("cp.async.bulk.shared::cta.global.mbarrier::complete_tx::bytes "
                 "[%0], [%1], %2, [%3];"
                 :: "r"(dst), "l"(src), "r"(bytes), "r"(mb) : "memory");
}
__device__ __forceinline__ void mbar_wait(uint32_t mb, uint32_t parity) {
    asm volatile(
        "{\n\t"
        ".reg .pred P;\n\t"
        "WAIT_%=:\n\t"
        "mbarrier.try_wait.parity.acquire.cta.shared::cta.b64 P, [%0], %1, 0x989680;\n\t"
        "@P bra.uni DONE_%=;\n\t"
        "bra.uni WAIT_%=;\n\t"
        "DONE_%=:\n\t"
        "}"
        :: "r"(mb), "r"(parity) : "memory");
}

template <int ACCUM>
__global__ __launch_bounds__(256, 2)
void tf32_gemm(GemmSegs segs, int nseg, int M, int K) {
    extern __shared__ float smem[];
    __shared__ uint64_t mbar[STAGES];

    int bx = blockIdx.x, si = 0;
    while (si + 1 < nseg && bx >= segs.s[si].tiles) { bx -= segs.s[si].tiles; si++; }
    const float* __restrict__ A = segs.s[si].A;
    const float* __restrict__ B = segs.s[si].B;
    float* __restrict__ C = segs.s[si].C;
    const int N   = segs.s[si].N;
    const int lda = segs.s[si].lda;
    const int n0  = bx * 64;
    const int m0  = blockIdx.y * 128;

    const int tid  = threadIdx.x;
    const int lane = tid & 31;
    const int warp = tid >> 5;
    const int wm   = warp >> 1;
    const int wn   = warp & 1;
    const int gid  = lane >> 2;
    const int tig  = lane & 3;

    uint32_t smBase = (uint32_t)__cvta_generic_to_shared(smem);
    uint32_t mbBase = (uint32_t)__cvta_generic_to_shared(&mbar[0]);

    if (tid == 0)
        for (int s = 0; s < STAGES; s++) mbar_init(mbBase + s * 8, 1);
    __syncthreads();

    const int nk = (K + GBK - 1) / GBK;
    const int nw = (N - n0 < 64) ? (N - n0) : 64;   // valid N cols this tile
    const uint32_t bw = (uint32_t)nw * 4u;          // bulk width per B row

    auto issue = [&](int kt) {
        const int st = kt % STAGES;
        const uint32_t mb = mbBase + st * 8;
        const uint32_t stOff = smBase + (uint32_t)(st * STAGEF) * 4u;
        const int k0 = kt * GBK;
        const int vb = (K - k0 < GBK) ? (K - k0) : GBK;   // valid B rows
        if (tid == 0) mbar_expect(mb, 16384u + (uint32_t)vb * bw);
        if (tid < 128) {
            const float* src = A + (size_t)(m0 + tid) * lda + k0;
            bulk_g2s(stOff + (uint32_t)tid * (ASTRIDE * 4), src, 128, mb);
        } else if (tid < 160) {
            const int r = tid - 128;
            if (r < vb) {
                bulk_g2s(stOff + (uint32_t)(SA + r * BSTRIDE) * 4u,
                         B + (size_t)(k0 + r) * N + n0, bw, mb);
            } else {
                // zero invalid K rows so they contribute exactly 0
                float4* p = (float4*)(smem + st * STAGEF + SA + r * BSTRIDE);
#pragma unroll
                for (int i = 0; i < 16; i++) p[i] = make_float4(0.f, 0.f, 0.f, 0.f);
            }
        }
    };

    for (int kt = 0; kt < STAGES && kt < nk; kt++) issue(kt);
    __syncthreads();   // make prologue STS zero-fills visible to all consumers

    float c[2][4][4] = {};

    for (int kt = 0; kt < nk; kt++) {
        const int st = kt % STAGES;
        mbar_wait(mbBase + st * 8, (kt / STAGES) & 1);

        const float* as = smem + st * STAGEF;
        const float* bs = as + SA;

#pragma unroll
        for (int kk = 0; kk < GBK; kk += 8) {
            uint32_t a[2][4];
#pragma unroll
            for (int mt = 0; mt < 2; mt++) {
                int mb2 = wm * 32 + mt * 16;
                a[mt][0] = f2tf32(as[(mb2 + gid    ) * ASTRIDE + kk + tig    ]);
                a[mt][1] = f2tf32(as[(mb2 + gid + 8) * ASTRIDE + kk + tig    ]);
                a[mt][2] = f2tf32(as[(mb2 + gid    ) * ASTRIDE + kk + tig + 4]);
                a[mt][3] = f2tf32(as[(mb2 + gid + 8) * ASTRIDE + kk + tig + 4]);
            }
            uint32_t b[4][2];
#pragma unroll
            for (int nt = 0; nt < 4; nt++) {
                int nn = wn * 32 + nt * 8 + gid;
                b[nt][0] = f2tf32(bs[(kk + tig    ) * BSTRIDE + nn]);
                b[nt][1] = f2tf32(bs[(kk + tig + 4) * BSTRIDE + nn]);
            }
#pragma unroll
            for (int mt = 0; mt < 2; mt++)
#pragma unroll
                for (int nt = 0; nt < 4; nt++) {
                    asm volatile(
                        "mma.sync.aligned.m16n8k8.row.col.f32.tf32.tf32.f32 "
                        "{%0,%1,%2,%3}, {%4,%5,%6,%7}, {%8,%9}, {%0,%1,%2,%3};"
                        : "+f"(c[mt][nt][0]), "+f"(c[mt][nt][1]),
                          "+f"(c[mt][nt][2]), "+f"(c[mt][nt][3])
                        : "r"(a[mt][0]), "r"(a[mt][1]),
                          "r"(a[mt][2]), "r"(a[mt][3]),
                          "r"(b[nt][0]), "r"(b[nt][1]));
                }
        }
        __syncthreads();
        if (kt + STAGES < nk) issue(kt + STAGES);
    }

#pragma unroll
    for (int mt = 0; mt < 2; mt++) {
#pragma unroll
        for (int nt = 0; nt < 4; nt++) {
            int gm = m0 + wm * 32 + mt * 16 + gid;
            int gn = n0 + wn * 32 + nt * 8 + tig * 2;
            if (gn < N) {
                size_t o0 = (size_t)gm * N + gn;
                size_t o1 = (size_t)(gm + 8) * N + gn;
                if (ACCUM) {
                    C[o0]     += c[mt][nt][0];
                    C[o0 + 1] += c[mt][nt][1];
                    C[o1]     += c[mt][nt][2];
                    C[o1 + 1] += c[mt][nt][3];
                } else {
                    C[o0]     = c[mt][nt][0];
                    C[o0 + 1] = c[mt][nt][1];
                    C[o1]     = c[mt][nt][2];
                    C[o1 + 1] = c[mt][nt][3];
                }
            }
        }
    }
}

static inline GemmSeg mkseg(const float* A, int lda, const float* B, float* C, int N) {
    GemmSeg s; s.A = A; s.lda = lda; s.B = B; s.C = C; s.N = N;
    s.tiles = (N + 63) / 64;
    return s;
}

static void gemmN(const GemmSegs& gs, int nseg, int M, int K, bool accum,
                  cudaStream_t st) {
    int tiles = 0;
    for (int i = 0; i < nseg; i++) tiles += gs.s[i].tiles;
    dim3 grid(tiles, M / 128);
    if (accum) tf32_gemm<1><<<grid, 256, GEMM_SMEM, st>>>(gs, nseg, M, K);
    else       tf32_gemm<0><<<grid, 256, GEMM_SMEM, st>>>(gs, nseg, M, K);
}

static void gemm1(const float* A, int lda, const float* B, float* C, int M,
                  int N, int K, bool accum, cudaStream_t st) {
    GemmSegs gs = {};
    gs.s[0] = mkseg(A, lda, B, C, N);
    gemmN(gs, 1, M, K, accum, st);
}

// ---------------- RMSNorm (zero-pads output rows to ypad) ----------------
__global__ void rmsnorm_kernel(const float* __restrict__ x,
                               const float* __restrict__ w,
                               float* __restrict__ y, int D, int ypad) {
    const int row = blockIdx.x;
    const float* xr = x + (size_t)row * D;
    float ss = 0.f;
    for (int i = threadIdx.x; i < D; i += 256) { float v = xr[i]; ss += v * v; }
    __shared__ float red[256];
    red[threadIdx.x] = ss;
    __syncthreads();
    for (int s = 128; s > 0; s >>= 1) {
        if (threadIdx.x < s) red[threadIdx.x] += red[threadIdx.x + s];
        __syncthreads();
    }
    float r = rsqrtf(red[0] / (float)D + 1e-5f);
    float* yr = y + (size_t)row * ypad;
    for (int i = threadIdx.x; i < D; i += 256) yr[i] = w[i] * xr[i] * r;
    for (int i = D + threadIdx.x; i < ypad; i += 256) yr[i] = 0.f;
}

// ---------------- RoPE (in place, pos = pos_base + row) ----------------
__global__ void rope_kernel(float* __restrict__ x, int nrows, int nheads,
                            int pos_base) {
    int idx = blockIdx.x * blockDim.x + threadIdx.x;
    int total = nrows * nheads * 32;
    if (idx >= total) return;
    int d = idx & 31;
    int h = (idx >> 5) % nheads;
    int r = idx / (32 * nheads);
    float pos = (float)(pos_base + r);
    float ts = powf(10000.f, (float)d * (1.f / 32.f));
    float rad = pos / ts;
    float s, c;
    sincosf(rad, &s, &c);
    float* p = x + ((size_t)r * nheads + h) * HD;
    float x1 = p[d], x2 = p[d + 32];
    p[d]      = x1 * c - x2 * s;
    p[d + 32] = x2 * c + x1 * s;
}

// ---------------- Attention (SIMT fp32) ----------------
__global__ __launch_bounds__(128)
void attn_kernel(const float* __restrict__ q, const float* __restrict__ k,
                 const float* __restrict__ v, float* __restrict__ out,
                 int nk, int prefix) {
    const int qi  = blockIdx.x;
    const int h   = blockIdx.y;
    const int kvh = h / 3;
    const int tid = threadIdx.x;

    __shared__ float qs[HD];
    __shared__ float sc[SS];
    __shared__ float red[128];

    const float* qr = q + ((size_t)qi * NH + h) * HD;
    if (tid < HD) qs[tid] = qr[tid];
    __syncthreads();

    int kmax = nk;
    if (prefix) kmax = (qi + 1 > prefix) ? (qi + 1) : prefix;

    const float4* q4 = (const float4*)qs;
    float mx = -1e30f;
    for (int j = tid; j < kmax; j += 128) {
        const float4* k4 = (const float4*)(k + ((size_t)j * NKV + kvh) * HD);
        float dot = 0.f;
#pragma unroll
        for (int d = 0; d < 16; d++) {
            float4 kk = k4[d], qq = q4[d];
            dot += qq.x * kk.x + qq.y * kk.y + qq.z * kk.z + qq.w * kk.w;
        }
        dot *= 0.125f;
        sc[j] = dot;
        mx = fmaxf(mx, dot);
    }
    red[tid] = mx;
    __syncthreads();
    for (int s = 64; s > 0; s >>= 1) {
        if (tid < s) red[tid] = fmaxf(red[tid], red[tid + s]);
        __syncthreads();
    }
    mx = red[0];
    __syncthreads();

    float sum = 0.f;
    for (int j = tid; j < kmax; j += 128) {
        float e = expf(sc[j] - mx);
        sc[j] = e;
        sum += e;
    }
    red[tid] = sum;
    __syncthreads();
    for (int s = 64; s > 0; s >>= 1) {
        if (tid < s) red[tid] += red[tid + s];
        __syncthreads();
    }
    float inv = 1.f / red[0];
    __syncthreads();

    const int d = tid & 63;
    const int half = tid >> 6;
    float acc = 0.f;
    for (int j = half; j < kmax; j += 2)
        acc += sc[j] * v[((size_t)j * NKV + kvh) * HD + d];
    red[tid] = acc;
    __syncthreads();
    if (tid < HD)
        out[((size_t)qi * NH + h) * HD + d] = (red[tid] + red[tid + 64]) * inv;
}

// ---------------- silu(g) * u ----------------
__global__ void silu_mul_kernel(const float* __restrict__ g,
                                const float* __restrict__ u,
                                float* __restrict__ m, int n) {
    int i = blockIdx.x * blockDim.x + threadIdx.x;
    if (i < n) {
        float x = g[i];
        float s = x / (1.f + expf(-x));
        m[i] = s * u[i];
    }
}

// ---------------- launch ----------------
static float* sym(const void* s) {
    void* p = nullptr;
    cudaGetSymbolAddress(&p, s);
    return (float*)p;
}

static cudaStream_t s2;
static cudaEvent_t ev0, evA[LAYERS], evB[LAYERS], evK[LAYERS],
                   evX[LAYERS], evR[LAYERS], evE;
static bool g_inited = false;

static void init_once() {
    if (g_inited) return;
    cudaStreamCreateWithFlags(&s2, cudaStreamNonBlocking);
    cudaEventCreateWithFlags(&ev0, cudaEventDisableTiming);
    cudaEventCreateWithFlags(&evE, cudaEventDisableTiming);
    for (int i = 0; i < LAYERS; i++) {
        cudaEventCreateWithFlags(&evA[i], cudaEventDisableTiming);
        cudaEventCreateWithFlags(&evB[i], cudaEventDisableTiming);
        cudaEventCreateWithFlags(&evK[i], cudaEventDisableTiming);
        cudaEventCreateWithFlags(&evX[i], cudaEventDisableTiming);
        cudaEventCreateWithFlags(&evR[i], cudaEventDisableTiming);
    }
    cudaFuncSetAttribute(tf32_gemm<0>, cudaFuncAttributeMaxDynamicSharedMemorySize, GEMM_SMEM);
    cudaFuncSetAttribute(tf32_gemm<1>, cudaFuncAttributeMaxDynamicSharedMemorySize, GEMM_SMEM);
    g_inited = true;
}

extern "C" void kernel_launch(void* const* d_in, const int* in_sizes, int n_in,
                              void* d_out, int out_size) {
    init_once();
    cudaStream_t s0 = 0;

    const float* vlm_embeds    = (const float*)d_in[0];
    const float* expert_embeds = (const float*)d_in[1];
    const float* w_vlm_q       = (const float*)d_in[2];
    const float* w_vlm_k       = (const float*)d_in[3];
    const float* w_vlm_v       = (const float*)d_in[4];
    const float* w_vlm_o       = (const float*)d_in[5];
    const float* w_vlm_ln1     = (const float*)d_in[6];
    const float* w_vlm_ln2     = (const float*)d_in[7];
    const float* w_vlm_gate    = (const float*)d_in[8];
    const float* w_vlm_up      = (const float*)d_in[9];
    const float* w_vlm_down    = (const float*)d_in[10];
    const float* w_vlm_fnorm   = (const float*)d_in[11];
    const float* w_exp_q       = (const float*)d_in[12];
    const float* w_exp_k_self  = (const float*)d_in[13];
    const float* w_exp_v_self  = (const float*)d_in[14];
    const float* w_exp_k_cross = (const float*)d_in[15];
    const float* w_exp_v_cross = (const float*)d_in[16];
    const float* w_exp_o       = (const float*)d_in[17];
    const float* w_exp_ln1     = (const float*)d_in[18];
    const float* w_exp_ln2     = (const float*)d_in[19];
    const float* w_exp_gate    = (const float*)d_in[20];
    const float* w_exp_up      = (const float*)d_in[21];
    const float* w_exp_down    = (const float*)d_in[22];
    const float* w_exp_fnorm   = (const float*)d_in[23];

    float* vlm = sym(g_vlm);
    float* exq = sym(g_exp);
    float* hv  = sym(g_hv);
    float* he  = sym(g_he);
    float* q   = sym(g_q);
    float* k   = sym(g_k);
    float* v   = sym(g_v);
    float* ke  = sym(g_ke);
    float* ve  = sym(g_ve);
    float* att = sym(g_att);
    float* gg  = sym(g_g);
    float* gu  = sym(g_u);
    float* gge = sym(g_ge);
    float* gue = sym(g_ue);

    cudaMemcpyAsync(vlm, vlm_embeds,    (size_t)PL * TH * sizeof(float),
                    cudaMemcpyDeviceToDevice, s0);
    cudaMemcpyAsync(exq, expert_embeds, (size_t)EL * EH * sizeof(float),
                    cudaMemcpyDeviceToDevice, s0);
    cudaEventRecord(ev0, s0);
    cudaStreamWaitEvent(s2, ev0, 0);

    for (int li = 0; li < LAYERS; li++) {
        if ((li & 1) == 0) {
            // ======== EVEN: joint attention over S=640 ========
            // s2: expert QKV (rows [PL,SS))
            rmsnorm_kernel<<<EL, 256, 0, s2>>>(exq, w_exp_ln1 + (size_t)li * EH, he, EH, EHP);
            {
                GemmSegs gs = {};
                gs.s[0] = mkseg(he, EHP, w_exp_q      + (size_t)li * EH * (NH * HD),       q + PL * NH * HD,  NH * HD);
                gs.s[1] = mkseg(he, EHP, w_exp_k_self + (size_t)(li / 2) * EH * (NKV * HD), k + PL * NKV * HD, NKV * HD);
                gs.s[2] = mkseg(he, EHP, w_exp_v_self + (size_t)(li / 2) * EH * (NKV * HD), v + PL * NKV * HD, NKV * HD);
                gemmN(gs, 3, EL, EH, false, s2);
            }
            cudaEventRecord(evA[li], s2);

            // s0: vlm QKV
            if (li > 0) cudaStreamWaitEvent(s0, evX[li - 1], 0);
            rmsnorm_kernel<<<PL, 256, 0, s0>>>(vlm, w_vlm_ln1 + (size_t)li * TH, hv, TH, TH);
            {
                GemmSegs gs = {};
                gs.s[0] = mkseg(hv, TH, w_vlm_q + (size_t)li * TH * (NH * HD),  q, NH * HD);
                gs.s[1] = mkseg(hv, TH, w_vlm_k + (size_t)li * TH * (NKV * HD), k, NKV * HD);
                gs.s[2] = mkseg(hv, TH, w_vlm_v + (size_t)li * TH * (NKV * HD), v, NKV * HD);
                gemmN(gs, 3, PL, TH, false, s0);
            }

            cudaStreamWaitEvent(s0, evA[li], 0);
            { int t = SS * NH * 32;  rope_kernel<<<(t + 255) / 256, 256, 0, s0>>>(q, SS, NH, 0); }
            { int t = SS * NKV * 32; rope_kernel<<<(t + 255) / 256, 256, 0, s0>>>(k, SS, NKV, 0); }
            if (li > 0) cudaStreamWaitEvent(s0, evR[li - 1], 0);
            attn_kernel<<<dim3(SS, NH), 128, 0, s0>>>(q, k, v, att, SS, PL);
            cudaEventRecord(evB[li], s0);

            // s2: expert block_out
            cudaStreamWaitEvent(s2, evB[li], 0);
            gemm1(att + PL * NH * HD, NH * HD, w_exp_o + (size_t)li * (NH * HD) * EH,
                  exq, EL, EH, NH * HD, true, s2);
            rmsnorm_kernel<<<EL, 256, 0, s2>>>(exq, w_exp_ln2 + (size_t)li * EH, he, EH, EHP);
            {
                GemmSegs gs = {};
                gs.s[0] = mkseg(he, EHP, w_exp_gate + (size_t)li * EH * EI, gge, EI);
                gs.s[1] = mkseg(he, EHP, w_exp_up   + (size_t)li * EH * EI, gue, EI);
                gemmN(gs, 2, EL, EH, false, s2);
            }
            silu_mul_kernel<<<(EL * EI + 255) / 256, 256, 0, s2>>>(gge, gue, gge, EL * EI);
            gemm1(gge, EI, w_exp_down + (size_t)li * EI * EH, exq, EL, EH, EI, true, s2);

            // s0: vlm block_out
            gemm1(att, NH * HD, w_vlm_o + (size_t)li * (NH * HD) * TH, vlm, PL, TH, NH * HD, true, s0);
            rmsnorm_kernel<<<PL, 256, 0, s0>>>(vlm, w_vlm_ln2 + (size_t)li * TH, hv, TH, TH);
            {
                GemmSegs gs = {};
                gs.s[0] = mkseg(hv, TH, w_vlm_gate + (size_t)li * TH * TI, gg, TI);
                gs.s[1] = mkseg(hv, TH, w_vlm_up   + (size_t)li * TH * TI, gu, TI);
                gemmN(gs, 2, PL, TH, false, s0);
            }
            silu_mul_kernel<<<(PL * TI + 255) / 256, 256, 0, s0>>>(gg, gu, gg, PL * TI);
            gemm1(gg, TI, w_vlm_down + (size_t)li * TI * TH, vlm, PL, TH, TI, true, s0);
        } else {
            // ======== ODD: vlm self-attn + expert cross-attn ========
            // s0: vlm QKV + rope (rows [0,PL))
            rmsnorm_kernel<<<PL, 256, 0, s0>>>(vlm, w_vlm_ln1 + (size_t)li * TH, hv, TH, TH);
            {
                GemmSegs gs = {};
                gs.s[0] = mkseg(hv, TH, w_vlm_q + (size_t)li * TH * (NH * HD),  q, NH * HD);
                gs.s[1] = mkseg(hv, TH, w_vlm_k + (size_t)li * TH * (NKV * HD), k, NKV * HD);
                gs.s[2] = mkseg(hv, TH, w_vlm_v + (size_t)li * TH * (NKV * HD), v, NKV * HD);
                gemmN(gs, 3, PL, TH, false, s0);
            }
            { int t = PL * NH * 32;  rope_kernel<<<(t + 255) / 256, 256, 0, s0>>>(q, PL, NH, 0); }
            { int t = PL * NKV * 32; rope_kernel<<<(t + 255) / 256, 256, 0, s0>>>(k, PL, NKV, 0); }
            cudaEventRecord(evK[li], s0);

            // s2: expert q + rope, cross K/V, attn, block_out
            rmsnorm_kernel<<<EL, 256, 0, s2>>>(exq, w_exp_ln1 + (size_t)li * EH, he, EH, EHP);
            gemm1(he, EHP, w_exp_q + (size_t)li * EH * (NH * HD), q + PL * NH * HD,
                  EL, NH * HD, EH, false, s2);
            { int t = EL * NH * 32; rope_kernel<<<(t + 255) / 256, 256, 0, s2>>>(q + PL * NH * HD, EL, NH, PL); }
            cudaStreamWaitEvent(s2, evK[li], 0);
            {
                GemmSegs gs = {};
                gs.s[0] = mkseg(k, NKV * HD, w_exp_k_cross + (size_t)(li / 2) * (NKV * HD) * (NKV * HD), ke, NKV * HD);
                gs.s[1] = mkseg(v, NKV * HD, w_exp_v_cross + (size_t)(li / 2) * (NKV * HD) * (NKV * HD), ve, NKV * HD);
                gemmN(gs, 2, PL, NKV * HD, false, s2);
            }
            cudaEventRecord(evX[li], s2);
            attn_kernel<<<dim3(EL, NH), 128, 0, s2>>>(q + PL * NH * HD, ke, ve,
                                                      att + PL * NH * HD, PL, 0);
            gemm1(att + PL * NH * HD, NH * HD, w_exp_o + (size_t)li * (NH * HD) * EH,
                  exq, EL, EH, NH * HD, true, s2);
            cudaEventRecord(evR[li], s2);
            rmsnorm_kernel<<<EL, 256, 0, s2>>>(exq, w_exp_ln2 + (size_t)li * EH, he, EH, EHP);
            {
                GemmSegs gs = {};
                gs.s[0] = mkseg(he, EHP, w_exp_gate + (size_t)li * EH * EI, gge, EI);
                gs.s[1] = mkseg(he, EHP, w_exp_up   + (size_t)li * EH * EI, gue, EI);
                gemmN(gs, 2, EL, EH, false, s2);
            }
            silu_mul_kernel<<<(EL * EI + 255) / 256, 256, 0, s2>>>(gge, gue, gge, EL * EI);
            gemm1(gge, EI, w_exp_down + (size_t)li * EI * EH, exq, EL, EH, EI, true, s2);
            if (li == LAYERS - 1) cudaEventRecord(evE, s2);

            // s0: vlm attention + block_out
            attn_kernel<<<dim3(PL, NH), 128, 0, s0>>>(q, k, v, att, PL, 0);
            gemm1(att, NH * HD, w_vlm_o + (size_t)li * (NH * HD) * TH, vlm, PL, TH, NH * HD, true, s0);
            rmsnorm_kernel<<<PL, 256, 0, s0>>>(vlm, w_vlm_ln2 + (size_t)li * TH, hv, TH, TH);
            {
                GemmSegs gs = {};
                gs.s[0] = mkseg(hv, TH, w_vlm_gate + (size_t)li * TH * TI, gg, TI);
                gs.s[1] = mkseg(hv, TH, w_vlm_up   + (size_t)li * TH * TI, gu, TI);
                gemmN(gs, 2, PL, TH, false, s0);
            }
            silu_mul_kernel<<<(PL * TI + 255) / 256, 256, 0, s0>>>(gg, gu, gg, PL * TI);
            gemm1(gg, TI, w_vlm_down + (size_t)li * TI * TH, vlm, PL, TH, TI, true, s0);
        }
    }

    // join expert stream, final norms
    cudaStreamWaitEvent(s0, evE, 0);
    float* out = (float*)d_out;
    rmsnorm_kernel<<<PL, 256, 0, s0>>>(vlm, w_vlm_fnorm, out, TH, TH);
    rmsnorm_kernel<<<EL, 256, 0, s0>>>(exq, w_exp_fnorm, out + (size_t)PL * TH, EH, EH);
}

// round 10
// speedup vs baseline: 2.1043x; 2.1043x over previous
#include <cuda_runtime.h>
#include <math.h>
#include <stdint.h>

#define PL 512
#define EL 128
#define SS 640
#define TH 960
#define EH 720
#define TI 2560
#define EI 2048
#define NH 15
#define NKV 5
#define HD 64
#define LAYERS 16

// ---------------- scratch (device globals) ----------------
__device__ __align__(256) float g_vlm[PL * TH];
__device__ __align__(256) float g_exp[EL * EH];
__device__ __align__(256) float g_hv [PL * TH];
__device__ __align__(256) float g_he [EL * EH];
__device__ __align__(256) float g_q  [SS * NH * HD];
__device__ __align__(256) float g_k  [SS * NKV * HD];
__device__ __align__(256) float g_v  [SS * NKV * HD];
__device__ __align__(256) float g_ke [PL * NKV * HD];
__device__ __align__(256) float g_ve [PL * NKV * HD];
__device__ __align__(256) float g_att[SS * NH * HD];
__device__ __align__(256) float g_g  [PL * TI];
__device__ __align__(256) float g_u  [PL * TI];
__device__ __align__(256) float g_ge [EL * EI];
__device__ __align__(256) float g_ue [EL * EI];

// ================= pipelined TF32 tensor-core GEMM (round-4 design) =======
// Block tile 128x64, BK=32, 256 threads = 8 warps (warp tile 32x32),
// 3-stage cp.async pipeline, multi-segment launches (up to 3 GEMMs sharing
// M and K; each segment has its own A, B, C, N).
// Requires M % 128 == 0, K % 4 == 0, N % 4 == 0.

#define GBK 32
#define ASTRIDE 36
#define BSTRIDE 72
#define AFLOATS (128 * ASTRIDE)      // 4608 floats per stage
#define BFLOATS (GBK * BSTRIDE)      // 2304 floats per stage
#define STAGES 3
#define GEMM_SMEM_BYTES (STAGES * (AFLOATS + BFLOATS) * 4)   // 82944

struct GemmSeg { const float* A; const float* B; float* C; int N; int tiles; };
struct GemmSegs { GemmSeg s[3]; };

__device__ __forceinline__ uint32_t f2tf32(float x) {
    uint32_t r;
    asm("cvt.rna.tf32.f32 %0, %1;" : "=r"(r) : "f"(x));
    return r;
}

__device__ __forceinline__ void cp_async16(uint32_t dst, const float* src, bool valid) {
    int sz = valid ? 16 : 0;
    asm volatile("cp.async.cg.shared.global [%0], [%1], 16, %2;\n"
                 :: "r"(dst), "l"(src), "r"(sz));
}

template <int ACCUM>
__global__ __launch_bounds__(256)
void tf32_gemm(GemmSegs segs, int nseg, int M, int K) {
    extern __shared__ float smem_dyn[];

    // segment select
    int bx = blockIdx.x, si = 0;
    while (si + 1 < nseg && bx >= segs.s[si].tiles) { bx -= segs.s[si].tiles; si++; }
    const float* __restrict__ A = segs.s[si].A;
    const float* __restrict__ B = segs.s[si].B;
    float* __restrict__ C = segs.s[si].C;
    const int N  = segs.s[si].N;
    const int n0 = bx * 64;
    const int m0 = blockIdx.y * 128;

    const int tid  = threadIdx.x;
    const int lane = tid & 31;
    const int warp = tid >> 5;
    const int wm   = warp >> 1;        // 0..3
    const int wn   = warp & 1;         // 0..1
    const int gid  = lane >> 2;        // 0..7
    const int tig  = lane & 3;         // 0..3

    // loader mapping
    const int am = tid >> 2;           // 0..63
    const int ak = (tid & 3) * 8;      // 0,8,16,24
    const int bk = tid >> 3;           // 0..31
    const int bn = (tid & 7) * 8;      // 0..56

    const float* aSrc0 = A + (size_t)(m0 + am) * K + ak;
    const float* aSrc1 = A + (size_t)(m0 + am + 64) * K + ak;
    const float* bSrc  = B + (size_t)bk * N + n0 + bn;

    const uint32_t base = (uint32_t)__cvta_generic_to_shared(smem_dyn);
    const uint32_t aD0 = base + (uint32_t)(am * ASTRIDE + ak) * 4u;
    const uint32_t aD1 = base + (uint32_t)((am + 64) * ASTRIDE + ak) * 4u;
    const uint32_t bD  = base + (uint32_t)(STAGES * AFLOATS + bk * BSTRIDE + bn) * 4u;

    const int nk = (K + GBK - 1) / GBK;
    const bool nv0 = (n0 + bn) < N;
    const bool nv1 = (n0 + bn + 4) < N;

    auto issue = [&](int kt) {
        const int st = kt % STAGES;
        const uint32_t aOff = (uint32_t)(st * AFLOATS) * 4u;
        const uint32_t bOff = (uint32_t)(st * BFLOATS) * 4u;
        const int k0 = kt * GBK;
        bool v0 = (k0 + ak) < K;
        bool v1 = (k0 + ak + 4) < K;
        cp_async16(aD0 + aOff,      v0 ? (aSrc0 + k0)     : A, v0);
        cp_async16(aD0 + aOff + 16, v1 ? (aSrc0 + k0 + 4) : A, v1);
        cp_async16(aD1 + aOff,      v0 ? (aSrc1 + k0)     : A, v0);
        cp_async16(aD1 + aOff + 16, v1 ? (aSrc1 + k0 + 4) : A, v1);
        bool kv = (k0 + bk) < K;
        const float* bs = bSrc + (size_t)k0 * N;
        cp_async16(bD + bOff,      (kv && nv0) ? bs       : B, kv && nv0);
        cp_async16(bD + bOff + 16, (kv && nv1) ? (bs + 4) : B, kv && nv1);
        asm volatile("cp.async.commit_group;\n" ::: "memory");
    };

    float c[2][4][4] = {};

    issue(0);
    if (nk > 1) issue(1);
    if (nk > 2) issue(2);

    for (int kt = 0; kt < nk; kt++) {
        int rem = nk - kt - 1;
        if (rem >= 2)      asm volatile("cp.async.wait_group 2;\n" ::: "memory");
        else if (rem == 1) asm volatile("cp.async.wait_group 1;\n" ::: "memory");
        else               asm volatile("cp.async.wait_group 0;\n" ::: "memory");
        __syncthreads();

        const float* as = smem_dyn + (kt % STAGES) * AFLOATS;
        const float* bs = smem_dyn + STAGES * AFLOATS + (kt % STAGES) * BFLOATS;

#pragma unroll
        for (int kk = 0; kk < GBK; kk += 8) {
            uint32_t a[2][4];
#pragma unroll
            for (int mt = 0; mt < 2; mt++) {
                int mb = wm * 32 + mt * 16;
                a[mt][0] = f2tf32(as[(mb + gid    ) * ASTRIDE + kk + tig    ]);
                a[mt][1] = f2tf32(as[(mb + gid + 8) * ASTRIDE + kk + tig    ]);
                a[mt][2] = f2tf32(as[(mb + gid    ) * ASTRIDE + kk + tig + 4]);
                a[mt][3] = f2tf32(as[(mb + gid + 8) * ASTRIDE + kk + tig + 4]);
            }
            uint32_t b[4][2];
#pragma unroll
            for (int nt = 0; nt < 4; nt++) {
                int nn = wn * 32 + nt * 8 + gid;
                b[nt][0] = f2tf32(bs[(kk + tig    ) * BSTRIDE + nn]);
                b[nt][1] = f2tf32(bs[(kk + tig + 4) * BSTRIDE + nn]);
            }
#pragma unroll
            for (int mt = 0; mt < 2; mt++)
#pragma unroll
                for (int nt = 0; nt < 4; nt++) {
                    asm volatile(
                        "mma.sync.aligned.m16n8k8.row.col.f32.tf32.tf32.f32 "
                        "{%0,%1,%2,%3}, {%4,%5,%6,%7}, {%8,%9}, {%0,%1,%2,%3};"
                        : "+f"(c[mt][nt][0]), "+f"(c[mt][nt][1]),
                          "+f"(c[mt][nt][2]), "+f"(c[mt][nt][3])
                        : "r"(a[mt][0]), "r"(a[mt][1]),
                          "r"(a[mt][2]), "r"(a[mt][3]),
                          "r"(b[nt][0]), "r"(b[nt][1]));
                }
        }
        __syncthreads();
        if (kt + STAGES < nk) issue(kt + STAGES);
    }

    // epilogue
#pragma unroll
    for (int mt = 0; mt < 2; mt++) {
#pragma unroll
        for (int nt = 0; nt < 4; nt++) {
            int gm = m0 + wm * 32 + mt * 16 + gid;
            int gn = n0 + wn * 32 + nt * 8 + tig * 2;
            if (gn < N) {
                size_t o0 = (size_t)gm * N + gn;
                size_t o1 = (size_t)(gm + 8) * N + gn;
                if (ACCUM) {
                    C[o0]     += c[mt][nt][0];
                    C[o0 + 1] += c[mt][nt][1];
                    C[o1]     += c[mt][nt][2];
                    C[o1 + 1] += c[mt][nt][3];
                } else {
                    C[o0]     = c[mt][nt][0];
                    C[o0 + 1] = c[mt][nt][1];
                    C[o1]     = c[mt][nt][2];
                    C[o1 + 1] = c[mt][nt][3];
                }
            }
        }
    }
}

static inline GemmSeg mkseg(const float* A, const float* B, float* C, int N) {
    GemmSeg s; s.A = A; s.B = B; s.C = C; s.N = N; s.tiles = (N + 63) / 64;
    return s;
}

static void gemmN(const GemmSegs& gs, int nseg, int M, int K, bool accum,
                  cudaStream_t st) {
    int tiles = 0;
    for (int i = 0; i < nseg; i++) tiles += gs.s[i].tiles;
    dim3 grid(tiles, M / 128);
    if (accum) tf32_gemm<1><<<grid, 256, GEMM_SMEM_BYTES, st>>>(gs, nseg, M, K);
    else       tf32_gemm<0><<<grid, 256, GEMM_SMEM_BYTES, st>>>(gs, nseg, M, K);
}

static void gemm1(const float* A, const float* B, float* C, int M, int N, int K,
                  bool accum, cudaStream_t st) {
    GemmSegs gs = {};
    gs.s[0] = mkseg(A, B, C, N);
    gemmN(gs, 1, M, K, accum, st);
}

// ---------------- RMSNorm ----------------
__global__ void rmsnorm_kernel(const float* __restrict__ x,
                               const float* __restrict__ w,
                               float* __restrict__ y, int D) {
    const int row = blockIdx.x;
    const float* xr = x + (size_t)row * D;
    float ss = 0.f;
    for (int i = threadIdx.x; i < D; i += 256) { float v = xr[i]; ss += v * v; }
    __shared__ float red[256];
    red[threadIdx.x] = ss;
    __syncthreads();
    for (int s = 128; s > 0; s >>= 1) {
        if (threadIdx.x < s) red[threadIdx.x] += red[threadIdx.x + s];
        __syncthreads();
    }
    float r = rsqrtf(red[0] / (float)D + 1e-5f);
    float* yr = y + (size_t)row * D;
    for (int i = threadIdx.x; i < D; i += 256) yr[i] = w[i] * xr[i] * r;
}

// ---------------- RoPE helpers (pos = row index) ----------------
__device__ __forceinline__ void rope_apply(float* x, int r, int h, int d,
                                           int nheads) {
    float pos = (float)r;
    float ts = powf(10000.f, (float)d * (1.f / 32.f));
    float rad = pos / ts;
    float s, c;
    sincosf(rad, &s, &c);
    float* p = x + ((size_t)r * nheads + h) * HD;
    float x1 = p[d], x2 = p[d + 32];
    p[d]      = x1 * c - x2 * s;
    p[d + 32] = x2 * c + x1 * s;
}

// single tensor (used for expert q with pos offset)
__global__ void rope_kernel(float* __restrict__ x, int nrows, int nheads,
                            int pos_base) {
    int idx = blockIdx.x * blockDim.x + threadIdx.x;
    int total = nrows * nheads * 32;
    if (idx >= total) return;
    int d = idx & 31;
    int h = (idx >> 5) % nheads;
    int r = idx / (32 * nheads);
    float pos = (float)(pos_base + r);
    float ts = powf(10000.f, (float)d * (1.f / 32.f));
    float rad = pos / ts;
    float s, c;
    sincosf(rad, &s, &c);
    float* p = x + ((size_t)r * nheads + h) * HD;
    float x1 = p[d], x2 = p[d + 32];
    p[d]      = x1 * c - x2 * s;
    p[d + 32] = x2 * c + x1 * s;
}

// fused q+k rope, pos_base = 0 for both (row index == position)
__global__ void rope_qk_kernel(float* __restrict__ q, int nq,
                               float* __restrict__ k, int nk2) {
    int idx = blockIdx.x * blockDim.x + threadIdx.x;
    int tq = nq * NH * 32;
    int tk = nk2 * NKV * 32;
    if (idx < tq) {
        int d = idx & 31;
        int h = (idx >> 5) % NH;
        int r = idx / (32 * NH);
        rope_apply(q, r, h, d, NH);
    } else if (idx < tq + tk) {
        int j = idx - tq;
        int d = j & 31;
        int h = (j >> 5) % NKV;
        int r = j / (32 * NKV);
        rope_apply(k, r, h, d, NKV);
    }
}

// ---------------- Attention (SIMT fp32) ----------------
__global__ __launch_bounds__(128)
void attn_kernel(const float* __restrict__ q, const float* __restrict__ k,
                 const float* __restrict__ v, float* __restrict__ out,
                 int nk, int prefix) {
    const int qi  = blockIdx.x;
    const int h   = blockIdx.y;
    const int kvh = h / 3;
    const int tid = threadIdx.x;

    __shared__ float qs[HD];
    __shared__ float sc[SS];
    __shared__ float red[128];

    const float* qr = q + ((size_t)qi * NH + h) * HD;
    if (tid < HD) qs[tid] = qr[tid];
    __syncthreads();

    int kmax = nk;
    if (prefix) kmax = (qi + 1 > prefix) ? (qi + 1) : prefix;

    const float4* q4 = (const float4*)qs;
    float mx = -1e30f;
    for (int j = tid; j < kmax; j += 128) {
        const float4* k4 = (const float4*)(k + ((size_t)j * NKV + kvh) * HD);
        float dot = 0.f;
#pragma unroll
        for (int d = 0; d < 16; d++) {
            float4 kk = k4[d], qq = q4[d];
            dot += qq.x * kk.x + qq.y * kk.y + qq.z * kk.z + qq.w * kk.w;
        }
        dot *= 0.125f;
        sc[j] = dot;
        mx = fmaxf(mx, dot);
    }
    red[tid] = mx;
    __syncthreads();
    for (int s = 64; s > 0; s >>= 1) {
        if (tid < s) red[tid] = fmaxf(red[tid], red[tid + s]);
        __syncthreads();
    }
    mx = red[0];
    __syncthreads();

    float sum = 0.f;
    for (int j = tid; j < kmax; j += 128) {
        float e = expf(sc[j] - mx);
        sc[j] = e;
        sum += e;
    }
    red[tid] = sum;
    __syncthreads();
    for (int s = 64; s > 0; s >>= 1) {
        if (tid < s) red[tid] += red[tid + s];
        __syncthreads();
    }
    float inv = 1.f / red[0];
    __syncthreads();

    const int d = tid & 63;
    const int half = tid >> 6;
    float acc = 0.f;
    for (int j = half; j < kmax; j += 2)
        acc += sc[j] * v[((size_t)j * NKV + kvh) * HD + d];
    red[tid] = acc;
    __syncthreads();
    if (tid < HD)
        out[((size_t)qi * NH + h) * HD + d] = (red[tid] + red[tid + 64]) * inv;
}

// ---------------- silu(g) * u ----------------
__global__ void silu_mul_kernel(const float* __restrict__ g,
                                const float* __restrict__ u,
                                float* __restrict__ m, int n) {
    int i = blockIdx.x * blockDim.x + threadIdx.x;
    if (i < n) {
        float x = g[i];
        float s = x / (1.f + expf(-x));
        m[i] = s * u[i];
    }
}

// ---------------- launch ----------------
static float* sym(const void* s) {
    void* p = nullptr;
    cudaGetSymbolAddress(&p, s);
    return (float*)p;
}

static cudaStream_t s2;
static cudaEvent_t ev0, evA[LAYERS], evB[LAYERS], evK[LAYERS],
                   evX[LAYERS], evR[LAYERS], evE;
static bool g_inited = false;

static void init_once() {
    if (g_inited) return;
    cudaStreamCreateWithFlags(&s2, cudaStreamNonBlocking);
    cudaEventCreateWithFlags(&ev0, cudaEventDisableTiming);
    cudaEventCreateWithFlags(&evE, cudaEventDisableTiming);
    for (int i = 0; i < LAYERS; i++) {
        cudaEventCreateWithFlags(&evA[i], cudaEventDisableTiming);
        cudaEventCreateWithFlags(&evB[i], cudaEventDisableTiming);
        cudaEventCreateWithFlags(&evK[i], cudaEventDisableTiming);
        cudaEventCreateWithFlags(&evX[i], cudaEventDisableTiming);
        cudaEventCreateWithFlags(&evR[i], cudaEventDisableTiming);
    }
    cudaFuncSetAttribute(tf32_gemm<0>, cudaFuncAttributeMaxDynamicSharedMemorySize, GEMM_SMEM_BYTES);
    cudaFuncSetAttribute(tf32_gemm<1>, cudaFuncAttributeMaxDynamicSharedMemorySize, GEMM_SMEM_BYTES);
    g_inited = true;
}

extern "C" void kernel_launch(void* const* d_in, const int* in_sizes, int n_in,
                              void* d_out, int out_size) {
    init_once();
    cudaStream_t s0 = 0;

    const float* vlm_embeds    = (const float*)d_in[0];
    const float* expert_embeds = (const float*)d_in[1];
    const float* w_vlm_q       = (const float*)d_in[2];
    const float* w_vlm_k       = (const float*)d_in[3];
    const float* w_vlm_v       = (const float*)d_in[4];
    const float* w_vlm_o       = (const float*)d_in[5];
    const float* w_vlm_ln1     = (const float*)d_in[6];
    const float* w_vlm_ln2     = (const float*)d_in[7];
    const float* w_vlm_gate    = (const float*)d_in[8];
    const float* w_vlm_up      = (const float*)d_in[9];
    const float* w_vlm_down    = (const float*)d_in[10];
    const float* w_vlm_fnorm   = (const float*)d_in[11];
    const float* w_exp_q       = (const float*)d_in[12];
    const float* w_exp_k_self  = (const float*)d_in[13];
    const float* w_exp_v_self  = (const float*)d_in[14];
    const float* w_exp_k_cross = (const float*)d_in[15];
    const float* w_exp_v_cross = (const float*)d_in[16];
    const float* w_exp_o       = (const float*)d_in[17];
    const float* w_exp_ln1     = (const float*)d_in[18];
    const float* w_exp_ln2     = (const float*)d_in[19];
    const float* w_exp_gate    = (const float*)d_in[20];
    const float* w_exp_up      = (const float*)d_in[21];
    const float* w_exp_down    = (const float*)d_in[22];
    const float* w_exp_fnorm   = (const float*)d_in[23];

    float* vlm = sym(g_vlm);
    float* exq = sym(g_exp);
    float* hv  = sym(g_hv);
    float* he  = sym(g_he);
    float* q   = sym(g_q);
    float* k   = sym(g_k);
    float* v   = sym(g_v);
    float* ke  = sym(g_ke);
    float* ve  = sym(g_ve);
    float* att = sym(g_att);
    float* gg  = sym(g_g);
    float* gu  = sym(g_u);
    float* gge = sym(g_ge);
    float* gue = sym(g_ue);

    cudaMemcpyAsync(vlm, vlm_embeds,    (size_t)PL * TH * sizeof(float),
                    cudaMemcpyDeviceToDevice, s0);
    cudaMemcpyAsync(exq, expert_embeds, (size_t)EL * EH * sizeof(float),
                    cudaMemcpyDeviceToDevice, s0);
    cudaEventRecord(ev0, s0);
    cudaStreamWaitEvent(s2, ev0, 0);

    for (int li = 0; li < LAYERS; li++) {
        if ((li & 1) == 0) {
            // ======== EVEN: joint attention over S=640 ========
            // s2: expert QKV (rows [PL,SS))
            rmsnorm_kernel<<<EL, 256, 0, s2>>>(exq, w_exp_ln1 + (size_t)li * EH, he, EH);
            {
                GemmSegs gs = {};
                gs.s[0] = mkseg(he, w_exp_q      + (size_t)li * EH * (NH * HD),        q + PL * NH * HD,  NH * HD);
                gs.s[1] = mkseg(he, w_exp_k_self + (size_t)(li / 2) * EH * (NKV * HD), k + PL * NKV * HD, NKV * HD);
                gs.s[2] = mkseg(he, w_exp_v_self + (size_t)(li / 2) * EH * (NKV * HD), v + PL * NKV * HD, NKV * HD);
                gemmN(gs, 3, EL, EH, false, s2);
            }
            cudaEventRecord(evA[li], s2);

            // s0: vlm QKV
            if (li > 0) cudaStreamWaitEvent(s0, evX[li - 1], 0);
            rmsnorm_kernel<<<PL, 256, 0, s0>>>(vlm, w_vlm_ln1 + (size_t)li * TH, hv, TH);
            {
                GemmSegs gs = {};
                gs.s[0] = mkseg(hv, w_vlm_q + (size_t)li * TH * (NH * HD),  q, NH * HD);
                gs.s[1] = mkseg(hv, w_vlm_k + (size_t)li * TH * (NKV * HD), k, NKV * HD);
                gs.s[2] = mkseg(hv, w_vlm_v + (size_t)li * TH * (NKV * HD), v, NKV * HD);
                gemmN(gs, 3, PL, TH, false, s0);
            }

            cudaStreamWaitEvent(s0, evA[li], 0);
            {
                int t = SS * NH * 32 + SS * NKV * 32;
                rope_qk_kernel<<<(t + 255) / 256, 256, 0, s0>>>(q, SS, k, SS);
            }
            if (li > 0) cudaStreamWaitEvent(s0, evR[li - 1], 0);
            attn_kernel<<<dim3(SS, NH), 128, 0, s0>>>(q, k, v, att, SS, PL);
            cudaEventRecord(evB[li], s0);

            // s2: expert block_out
            cudaStreamWaitEvent(s2, evB[li], 0);
            gemm1(att + PL * NH * HD, w_exp_o + (size_t)li * (NH * HD) * EH,
                  exq, EL, EH, NH * HD, true, s2);
            rmsnorm_kernel<<<EL, 256, 0, s2>>>(exq, w_exp_ln2 + (size_t)li * EH, he, EH);
            {
                GemmSegs gs = {};
                gs.s[0] = mkseg(he, w_exp_gate + (size_t)li * EH * EI, gge, EI);
                gs.s[1] = mkseg(he, w_exp_up   + (size_t)li * EH * EI, gue, EI);
                gemmN(gs, 2, EL, EH, false, s2);
            }
            silu_mul_kernel<<<(EL * EI + 255) / 256, 256, 0, s2>>>(gge, gue, gge, EL * EI);
            gemm1(gge, w_exp_down + (size_t)li * EI * EH, exq, EL, EH, EI, true, s2);

            // s0: vlm block_out
            gemm1(att, w_vlm_o + (size_t)li * (NH * HD) * TH, vlm, PL, TH, NH * HD, true, s0);
            rmsnorm_kernel<<<PL, 256, 0, s0>>>(vlm, w_vlm_ln2 + (size_t)li * TH, hv, TH);
            {
                GemmSegs gs = {};
                gs.s[0] = mkseg(hv, w_vlm_gate + (size_t)li * TH * TI, gg, TI);
                gs.s[1] = mkseg(hv, w_vlm_up   + (size_t)li * TH * TI, gu, TI);
                gemmN(gs, 2, PL, TH, false, s0);
            }
            silu_mul_kernel<<<(PL * TI + 255) / 256, 256, 0, s0>>>(gg, gu, gg, PL * TI);
            gemm1(gg, w_vlm_down + (size_t)li * TI * TH, vlm, PL, TH, TI, true, s0);
        } else {
            // ======== ODD: vlm self-attn + expert cross-attn ========
            // s0: vlm QKV + rope (rows [0,PL))
            rmsnorm_kernel<<<PL, 256, 0, s0>>>(vlm, w_vlm_ln1 + (size_t)li * TH, hv, TH);
            {
                GemmSegs gs = {};
                gs.s[0] = mkseg(hv, w_vlm_q + (size_t)li * TH * (NH * HD),  q, NH * HD);
                gs.s[1] = mkseg(hv, w_vlm_k + (size_t)li * TH * (NKV * HD), k, NKV * HD);
                gs.s[2] = mkseg(hv, w_vlm_v + (size_t)li * TH * (NKV * HD), v, NKV * HD);
                gemmN(gs, 3, PL, TH, false, s0);
            }
            {
                int t = PL * NH * 32 + PL * NKV * 32;
                rope_qk_kernel<<<(t + 255) / 256, 256, 0, s0>>>(q, PL, k, PL);
            }
            cudaEventRecord(evK[li], s0);

            // s2: expert q + rope, cross K/V, attn, block_out
            rmsnorm_kernel<<<EL, 256, 0, s2>>>(exq, w_exp_ln1 + (size_t)li * EH, he, EH);
            gemm1(he, w_exp_q + (size_t)li * EH * (NH * HD), q + PL * NH * HD,
                  EL, NH * HD, EH, false, s2);
            { int t = EL * NH * 32; rope_kernel<<<(t + 255) / 256, 256, 0, s2>>>(q + PL * NH * HD, EL, NH, PL); }
            cudaStreamWaitEvent(s2, evK[li], 0);
            {
                GemmSegs gs = {};
                gs.s[0] = mkseg(k, w_exp_k_cross + (size_t)(li / 2) * (NKV * HD) * (NKV * HD), ke, NKV * HD);
                gs.s[1] = mkseg(v, w_exp_v_cross + (size_t)(li / 2) * (NKV * HD) * (NKV * HD), ve, NKV * HD);
                gemmN(gs, 2, PL, NKV * HD, false, s2);
            }
            cudaEventRecord(evX[li], s2);
            attn_kernel<<<dim3(EL, NH), 128, 0, s2>>>(q + PL * NH * HD, ke, ve,
                                                      att + PL * NH * HD, PL, 0);
            gemm1(att + PL * NH * HD, w_exp_o + (size_t)li * (NH * HD) * EH,
                  exq, EL, EH, NH * HD, true, s2);
            cudaEventRecord(evR[li], s2);
            rmsnorm_kernel<<<EL, 256, 0, s2>>>(exq, w_exp_ln2 + (size_t)li * EH, he, EH);
            {
                GemmSegs gs = {};
                gs.s[0] = mkseg(he, w_exp_gate + (size_t)li * EH * EI, gge, EI);
                gs.s[1] = mkseg(he, w_exp_up   + (size_t)li * EH * EI, gue, EI);
                gemmN(gs, 2, EL, EH, false, s2);
            }
            silu_mul_kernel<<<(EL * EI + 255) / 256, 256, 0, s2>>>(gge, gue, gge, EL * EI);
            gemm1(gge, w_exp_down + (size_t)li * EI * EH, exq, EL, EH, EI, true, s2);
            if (li == LAYERS - 1) cudaEventRecord(evE, s2);

            // s0: vlm attention + block_out
            attn_kernel<<<dim3(PL, NH), 128, 0, s0>>>(q, k, v, att, PL, 0);
            gemm1(att, w_vlm_o + (size_t)li * (NH * HD) * TH, vlm, PL, TH, NH * HD, true, s0);
            rmsnorm_kernel<<<PL, 256, 0, s0>>>(vlm, w_vlm_ln2 + (size_t)li * TH, hv, TH);
            {
                GemmSegs gs = {};
                gs.s[0] = mkseg(hv, w_vlm_gate + (size_t)li * TH * TI, gg, TI);
                gs.s[1] = mkseg(hv, w_vlm_up   + (size_t)li * TH * TI, gu, TI);
                gemmN(gs, 2, PL, TH, false, s0);
            }
            silu_mul_kernel<<<(PL * TI + 255) / 256, 256, 0, s0>>>(gg, gu, gg, PL * TI);
            gemm1(gg, w_vlm_down + (size_t)li * TI * TH, vlm, PL, TH, TI, true, s0);
        }
    }

    // join expert stream, final norms
    cudaStreamWaitEvent(s0, evE, 0);
    float* out = (float*)d_out;
    rmsnorm_kernel<<<PL, 256, 0, s0>>>(vlm, w_vlm_fnorm, out, TH);
    rmsnorm_kernel<<<EL, 256, 0, s0>>>(exq, w_exp_fnorm, out + (size_t)PL * TH, EH);
}

// round 12
// speedup vs baseline: 3.4396x; 1.6345x over previous
#include <cuda_runtime.h>
#include <math.h>
#include <stdint.h>

#define PL 512
#define EL 128
#define SS 640
#define TH 960
#define EH 720
#define TI 2560
#define EI 2048
#define NH 15
#define NKV 5
#define HD 64
#define LAYERS 16

// ---------------- scratch (device globals) ----------------
__device__ __align__(256) float g_vlm[PL * TH];
__device__ __align__(256) float g_exp[EL * EH];
__device__ __align__(256) float g_hv [PL * TH];
__device__ __align__(256) float g_he [EL * EH];
__device__ __align__(256) float g_q  [SS * NH * HD];
__device__ __align__(256) float g_k  [SS * NKV * HD];
__device__ __align__(256) float g_v  [SS * NKV * HD];
__device__ __align__(256) float g_ke [PL * NKV * HD];
__device__ __align__(256) float g_ve [PL * NKV * HD];
__device__ __align__(256) float g_att[SS * NH * HD];
__device__ __align__(256) float g_g  [PL * TI];
__device__ __align__(256) float g_u  [PL * TI];
__device__ __align__(256) float g_ge [EL * EI];
__device__ __align__(256) float g_ue [EL * EI];

// ================= pipelined TF32 tensor-core GEMM (round-4 design) =======
#define GBK 32
#define ASTRIDE 36
#define BSTRIDE 72
#define AFLOATS (128 * ASTRIDE)
#define BFLOATS (GBK * BSTRIDE)
#define STAGES 3
#define GEMM_SMEM_BYTES (STAGES * (AFLOATS + BFLOATS) * 4)   // 82944

struct GemmSeg { const float* A; const float* B; float* C; int N; int tiles; };
struct GemmSegs { GemmSeg s[3]; };

__device__ __forceinline__ uint32_t f2tf32(float x) {
    uint32_t r;
    asm("cvt.rna.tf32.f32 %0, %1;" : "=r"(r) : "f"(x));
    return r;
}

__device__ __forceinline__ void cp_async16(uint32_t dst, const float* src, bool valid) {
    int sz = valid ? 16 : 0;
    asm volatile("cp.async.cg.shared.global [%0], [%1], 16, %2;\n"
                 :: "r"(dst), "l"(src), "r"(sz));
}

template <int ACCUM>
__global__ __launch_bounds__(256)
void tf32_gemm(GemmSegs segs, int nseg, int M, int K) {
    extern __shared__ float smem_dyn[];

    int bx = blockIdx.x, si = 0;
    while (si + 1 < nseg && bx >= segs.s[si].tiles) { bx -= segs.s[si].tiles; si++; }
    const float* __restrict__ A = segs.s[si].A;
    const float* __restrict__ B = segs.s[si].B;
    float* __restrict__ C = segs.s[si].C;
    const int N  = segs.s[si].N;
    const int n0 = bx * 64;
    const int m0 = blockIdx.y * 128;

    const int tid  = threadIdx.x;
    const int lane = tid & 31;
    const int warp = tid >> 5;
    const int wm   = warp >> 1;
    const int wn   = warp & 1;
    const int gid  = lane >> 2;
    const int tig  = lane & 3;

    const int am = tid >> 2;
    const int ak = (tid & 3) * 8;
    const int bk = tid >> 3;
    const int bn = (tid & 7) * 8;

    const float* aSrc0 = A + (size_t)(m0 + am) * K + ak;
    const float* aSrc1 = A + (size_t)(m0 + am + 64) * K + ak;
    const float* bSrc  = B + (size_t)bk * N + n0 + bn;

    const uint32_t base = (uint32_t)__cvta_generic_to_shared(smem_dyn);
    const uint32_t aD0 = base + (uint32_t)(am * ASTRIDE + ak) * 4u;
    const uint32_t aD1 = base + (uint32_t)((am + 64) * ASTRIDE + ak) * 4u;
    const uint32_t bD  = base + (uint32_t)(STAGES * AFLOATS + bk * BSTRIDE + bn) * 4u;

    const int nk = (K + GBK - 1) / GBK;
    const bool nv0 = (n0 + bn) < N;
    const bool nv1 = (n0 + bn + 4) < N;

    auto issue = [&](int kt) {
        const int st = kt % STAGES;
        const uint32_t aOff = (uint32_t)(st * AFLOATS) * 4u;
        const uint32_t bOff = (uint32_t)(st * BFLOATS) * 4u;
        const int k0 = kt * GBK;
        bool v0 = (k0 + ak) < K;
        bool v1 = (k0 + ak + 4) < K;
        cp_async16(aD0 + aOff,      v0 ? (aSrc0 + k0)     : A, v0);
        cp_async16(aD0 + aOff + 16, v1 ? (aSrc0 + k0 + 4) : A, v1);
        cp_async16(aD1 + aOff,      v0 ? (aSrc1 + k0)     : A, v0);
        cp_async16(aD1 + aOff + 16, v1 ? (aSrc1 + k0 + 4) : A, v1);
        bool kv = (k0 + bk) < K;
        const float* bs = bSrc + (size_t)k0 * N;
        cp_async16(bD + bOff,      (kv && nv0) ? bs       : B, kv && nv0);
        cp_async16(bD + bOff + 16, (kv && nv1) ? (bs + 4) : B, kv && nv1);
        asm volatile("cp.async.commit_group;\n" ::: "memory");
    };

    float c[2][4][4] = {};

    issue(0);
    if (nk > 1) issue(1);
    if (nk > 2) issue(2);

    for (int kt = 0; kt < nk; kt++) {
        int rem = nk - kt - 1;
        if (rem >= 2)      asm volatile("cp.async.wait_group 2;\n" ::: "memory");
        else if (rem == 1) asm volatile("cp.async.wait_group 1;\n" ::: "memory");
        else               asm volatile("cp.async.wait_group 0;\n" ::: "memory");
        __syncthreads();

        const float* as = smem_dyn + (kt % STAGES) * AFLOATS;
        const float* bs = smem_dyn + STAGES * AFLOATS + (kt % STAGES) * BFLOATS;

#pragma unroll
        for (int kk = 0; kk < GBK; kk += 8) {
            uint32_t a[2][4];
#pragma unroll
            for (int mt = 0; mt < 2; mt++) {
                int mb = wm * 32 + mt * 16;
                a[mt][0] = f2tf32(as[(mb + gid    ) * ASTRIDE + kk + tig    ]);
                a[mt][1] = f2tf32(as[(mb + gid + 8) * ASTRIDE + kk + tig    ]);
                a[mt][2] = f2tf32(as[(mb + gid    ) * ASTRIDE + kk + tig + 4]);
                a[mt][3] = f2tf32(as[(mb + gid + 8) * ASTRIDE + kk + tig + 4]);
            }
            uint32_t b[4][2];
#pragma unroll
            for (int nt = 0; nt < 4; nt++) {
                int nn = wn * 32 + nt * 8 + gid;
                b[nt][0] = f2tf32(bs[(kk + tig    ) * BSTRIDE + nn]);
                b[nt][1] = f2tf32(bs[(kk + tig + 4) * BSTRIDE + nn]);
            }
#pragma unroll
            for (int mt = 0; mt < 2; mt++)
#pragma unroll
                for (int nt = 0; nt < 4; nt++) {
                    asm volatile(
                        "mma.sync.aligned.m16n8k8.row.col.f32.tf32.tf32.f32 "
                        "{%0,%1,%2,%3}, {%4,%5,%6,%7}, {%8,%9}, {%0,%1,%2,%3};"
                        : "+f"(c[mt][nt][0]), "+f"(c[mt][nt][1]),
                          "+f"(c[mt][nt][2]), "+f"(c[mt][nt][3])
                        : "r"(a[mt][0]), "r"(a[mt][1]),
                          "r"(a[mt][2]), "r"(a[mt][3]),
                          "r"(b[nt][0]), "r"(b[nt][1]));
                }
        }
        __syncthreads();
        if (kt + STAGES < nk) issue(kt + STAGES);
    }

#pragma unroll
    for (int mt = 0; mt < 2; mt++) {
#pragma unroll
        for (int nt = 0; nt < 4; nt++) {
            int gm = m0 + wm * 32 + mt * 16 + gid;
            int gn = n0 + wn * 32 + nt * 8 + tig * 2;
            if (gn < N) {
                size_t o0 = (size_t)gm * N + gn;
                size_t o1 = (size_t)(gm + 8) * N + gn;
                if (ACCUM) {
                    C[o0]     += c[mt][nt][0];
                    C[o0 + 1] += c[mt][nt][1];
                    C[o1]     += c[mt][nt][2];
                    C[o1 + 1] += c[mt][nt][3];
                } else {
                    C[o0]     = c[mt][nt][0];
                    C[o0 + 1] = c[mt][nt][1];
                    C[o1]     = c[mt][nt][2];
                    C[o1 + 1] = c[mt][nt][3];
                }
            }
        }
    }
}

static inline GemmSeg mkseg(const float* A, const float* B, float* C, int N) {
    GemmSeg s; s.A = A; s.B = B; s.C = C; s.N = N; s.tiles = (N + 63) / 64;
    return s;
}

static void gemmN(const GemmSegs& gs, int nseg, int M, int K, bool accum,
                  cudaStream_t st) {
    int tiles = 0;
    for (int i = 0; i < nseg; i++) tiles += gs.s[i].tiles;
    dim3 grid(tiles, M / 128);
    if (accum) tf32_gemm<1><<<grid, 256, GEMM_SMEM_BYTES, st>>>(gs, nseg, M, K);
    else       tf32_gemm<0><<<grid, 256, GEMM_SMEM_BYTES, st>>>(gs, nseg, M, K);
}

static void gemm1(const float* A, const float* B, float* C, int M, int N, int K,
                  bool accum, cudaStream_t st) {
    GemmSegs gs = {};
    gs.s[0] = mkseg(A, B, C, N);
    gemmN(gs, 1, M, K, accum, st);
}

// ---------------- RMSNorm ----------------
__global__ void rmsnorm_kernel(const float* __restrict__ x,
                               const float* __restrict__ w,
                               float* __restrict__ y, int D) {
    const int row = blockIdx.x;
    const float* xr = x + (size_t)row * D;
    float ss = 0.f;
    for (int i = threadIdx.x; i < D; i += 256) { float v = xr[i]; ss += v * v; }
    __shared__ float red[256];
    red[threadIdx.x] = ss;
    __syncthreads();
    for (int s = 128; s > 0; s >>= 1) {
        if (threadIdx.x < s) red[threadIdx.x] += red[threadIdx.x + s];
        __syncthreads();
    }
    float r = rsqrtf(red[0] / (float)D + 1e-5f);
    float* yr = y + (size_t)row * D;
    for (int i = threadIdx.x; i < D; i += 256) yr[i] = w[i] * xr[i] * r;
}

// ---------------- RoPE ----------------
__device__ __forceinline__ void rope_apply(float* x, int r, int h, int d,
                                           int nheads) {
    float pos = (float)r;
    float ts = powf(10000.f, (float)d * (1.f / 32.f));
    float rad = pos / ts;
    float s, c;
    sincosf(rad, &s, &c);
    float* p = x + ((size_t)r * nheads + h) * HD;
    float x1 = p[d], x2 = p[d + 32];
    p[d]      = x1 * c - x2 * s;
    p[d + 32] = x2 * c + x1 * s;
}

__global__ void rope_kernel(float* __restrict__ x, int nrows, int nheads,
                            int pos_base) {
    int idx = blockIdx.x * blockDim.x + threadIdx.x;
    int total = nrows * nheads * 32;
    if (idx >= total) return;
    int d = idx & 31;
    int h = (idx >> 5) % nheads;
    int r = idx / (32 * nheads);
    float pos = (float)(pos_base + r);
    float ts = powf(10000.f, (float)d * (1.f / 32.f));
    float rad = pos / ts;
    float s, c;
    sincosf(rad, &s, &c);
    float* p = x + ((size_t)r * nheads + h) * HD;
    float x1 = p[d], x2 = p[d + 32];
    p[d]      = x1 * c - x2 * s;
    p[d + 32] = x2 * c + x1 * s;
}

__global__ void rope_qk_kernel(float* __restrict__ q, int nq,
                               float* __restrict__ k, int nk2) {
    int idx = blockIdx.x * blockDim.x + threadIdx.x;
    int tq = nq * NH * 32;
    int tk = nk2 * NKV * 32;
    if (idx < tq) {
        int d = idx & 31;
        int h = (idx >> 5) % NH;
        int r = idx / (32 * NH);
        rope_apply(q, r, h, d, NH);
    } else if (idx < tq + tk) {
        int j = idx - tq;
        int d = j & 31;
        int h = (j >> 5) % NKV;
        int r = j / (32 * NKV);
        rope_apply(k, r, h, d, NKV);
    }
}

// ================= tiled flash attention =================
// Block = (64-query tile, head). 256 threads: 4 per query (qi=tid>>2, c=tid&3).
// Q row cached in registers; K/V tiles staged via smem; online softmax.
// prefix==0: all nk keys visible. prefix>0: query g sees keys < max(prefix,g+1).
// Requires nq%64==0, nk%64==0.
#define KPAD 68
#define ATTN_SMEM (3 * 64 * KPAD * 4)   // ks, vs, ps = 52224 bytes

__global__ __launch_bounds__(256)
void attn_tile_kernel(const float* __restrict__ q, const float* __restrict__ k,
                      const float* __restrict__ v, float* __restrict__ out,
                      int nk, int prefix) {
    extern __shared__ float sm[];
    float* ks = sm;
    float* vs = sm + 64 * KPAD;
    float* ps = sm + 2 * 64 * KPAD;

    const int tid = threadIdx.x;
    const int qi  = tid >> 2;
    const int c   = tid & 3;
    const int h   = blockIdx.y;
    const int kvh = h / 3;
    const int q0  = blockIdx.x * 64;
    const int gq  = q0 + qi;

    // cache Q row in registers
    float4 qreg[16];
    const float4* qrow = (const float4*)(q + ((size_t)gq * NH + h) * HD);
#pragma unroll
    for (int i = 0; i < 16; i++) qreg[i] = qrow[i];

    float o[16];
#pragma unroll
    for (int i = 0; i < 16; i++) o[i] = 0.f;
    float m = -1e30f, l = 0.f;

    const int kmaxq = prefix ? ((gq + 1 > prefix) ? gq + 1 : prefix) : nk;
    const int kend  = prefix ? ((q0 + 64 > prefix) ? q0 + 64 : prefix) : nk;

    const int lrow = tid >> 2;          // K/V load row (0..63)
    const int lcol = (tid & 3) * 16;    // load col base

    for (int kt = 0; kt < kend; kt += 64) {
        __syncthreads();   // prev phase-2 reads of vs done
        {
            const float4* ksrc = (const float4*)(k + ((size_t)(kt + lrow) * NKV + kvh) * HD + lcol);
            const float4* vsrc = (const float4*)(v + ((size_t)(kt + lrow) * NKV + kvh) * HD + lcol);
            float4* kdst = (float4*)(ks + lrow * KPAD + lcol);
            float4* vdst = (float4*)(vs + lrow * KPAD + lcol);
#pragma unroll
            for (int i = 0; i < 4; i++) kdst[i] = ksrc[i];
#pragma unroll
            for (int i = 0; i < 4; i++) vdst[i] = vsrc[i];
        }
        __syncthreads();

        // phase 1: scores for keys j = 4*jj + c
        float s[16];
        float tmax = -1e30f;
#pragma unroll
        for (int jj = 0; jj < 16; jj++) {
            int j = 4 * jj + c;
            const float4* krow = (const float4*)(ks + j * KPAD);
            float dot = 0.f;
#pragma unroll
            for (int t = 0; t < 16; t++) {
                float4 kk = krow[t];
                dot += qreg[t].x * kk.x + qreg[t].y * kk.y
                     + qreg[t].z * kk.z + qreg[t].w * kk.w;
            }
            dot *= 0.125f;
            if (kt + j >= kmaxq) dot = -1e30f;
            s[jj] = dot;
            tmax = fmaxf(tmax, dot);
        }
        tmax = fmaxf(tmax, __shfl_xor_sync(0xffffffffu, tmax, 1));
        tmax = fmaxf(tmax, __shfl_xor_sync(0xffffffffu, tmax, 2));
        float mnew  = fmaxf(m, tmax);
        float scale = expf(m - mnew);

        float psum = 0.f;
#pragma unroll
        for (int jj = 0; jj < 16; jj++) {
            float e = expf(s[jj] - mnew);
            ps[qi * KPAD + 4 * jj + c] = e;
            psum += e;
        }
        psum += __shfl_xor_sync(0xffffffffu, psum, 1);
        psum += __shfl_xor_sync(0xffffffffu, psum, 2);
        l = l * scale + psum;
#pragma unroll
        for (int i = 0; i < 16; i++) o[i] *= scale;
        m = mnew;
        __syncthreads();

        // phase 2: o[d] += sum_j p[j] * V[j][d], d = c*16..c*16+15
#pragma unroll 16
        for (int j = 0; j < 64; j++) {
            float p = ps[qi * KPAD + j];
            const float4* vrow = (const float4*)(vs + j * KPAD + c * 16);
#pragma unroll
            for (int t = 0; t < 4; t++) {
                float4 vv = vrow[t];
                o[4 * t + 0] += p * vv.x;
                o[4 * t + 1] += p * vv.y;
                o[4 * t + 2] += p * vv.z;
                o[4 * t + 3] += p * vv.w;
            }
        }
    }

    float inv = 1.f / l;
    float* orow = out + ((size_t)gq * NH + h) * HD + c * 16;
#pragma unroll
    for (int i = 0; i < 16; i++) orow[i] = o[i] * inv;
}

// ---------------- silu(g) * u ----------------
__global__ void silu_mul_kernel(const float* __restrict__ g,
                                const float* __restrict__ u,
                                float* __restrict__ m, int n) {
    int i = blockIdx.x * blockDim.x + threadIdx.x;
    if (i < n) {
        float x = g[i];
        float s = x / (1.f + expf(-x));
        m[i] = s * u[i];
    }
}

// ---------------- launch ----------------
static float* sym(const void* s) {
    void* p = nullptr;
    cudaGetSymbolAddress(&p, s);
    return (float*)p;
}

static cudaStream_t s2;
static cudaEvent_t ev0, evA[LAYERS], evB[LAYERS], evK[LAYERS],
                   evX[LAYERS], evR[LAYERS], evE;
static bool g_inited = false;

static void init_once() {
    if (g_inited) return;
    cudaStreamCreateWithFlags(&s2, cudaStreamNonBlocking);
    cudaEventCreateWithFlags(&ev0, cudaEventDisableTiming);
    cudaEventCreateWithFlags(&evE, cudaEventDisableTiming);
    for (int i = 0; i < LAYERS; i++) {
        cudaEventCreateWithFlags(&evA[i], cudaEventDisableTiming);
        cudaEventCreateWithFlags(&evB[i], cudaEventDisableTiming);
        cudaEventCreateWithFlags(&evK[i], cudaEventDisableTiming);
        cudaEventCreateWithFlags(&evX[i], cudaEventDisableTiming);
        cudaEventCreateWithFlags(&evR[i], cudaEventDisableTiming);
    }
    cudaFuncSetAttribute(tf32_gemm<0>, cudaFuncAttributeMaxDynamicSharedMemorySize, GEMM_SMEM_BYTES);
    cudaFuncSetAttribute(tf32_gemm<1>, cudaFuncAttributeMaxDynamicSharedMemorySize, GEMM_SMEM_BYTES);
    cudaFuncSetAttribute(attn_tile_kernel, cudaFuncAttributeMaxDynamicSharedMemorySize, ATTN_SMEM);
    g_inited = true;
}

extern "C" void kernel_launch(void* const* d_in, const int* in_sizes, int n_in,
                              void* d_out, int out_size) {
    init_once();
    cudaStream_t s0 = 0;

    const float* vlm_embeds    = (const float*)d_in[0];
    const float* expert_embeds = (const float*)d_in[1];
    const float* w_vlm_q       = (const float*)d_in[2];
    const float* w_vlm_k       = (const float*)d_in[3];
    const float* w_vlm_v       = (const float*)d_in[4];
    const float* w_vlm_o       = (const float*)d_in[5];
    const float* w_vlm_ln1     = (const float*)d_in[6];
    const float* w_vlm_ln2     = (const float*)d_in[7];
    const float* w_vlm_gate    = (const float*)d_in[8];
    const float* w_vlm_up      = (const float*)d_in[9];
    const float* w_vlm_down    = (const float*)d_in[10];
    const float* w_vlm_fnorm   = (const float*)d_in[11];
    const float* w_exp_q       = (const float*)d_in[12];
    const float* w_exp_k_self  = (const float*)d_in[13];
    const float* w_exp_v_self  = (const float*)d_in[14];
    const float* w_exp_k_cross = (const float*)d_in[15];
    const float* w_exp_v_cross = (const float*)d_in[16];
    const float* w_exp_o       = (const float*)d_in[17];
    const float* w_exp_ln1     = (const float*)d_in[18];
    const float* w_exp_ln2     = (const float*)d_in[19];
    const float* w_exp_gate    = (const float*)d_in[20];
    const float* w_exp_up      = (const float*)d_in[21];
    const float* w_exp_down    = (const float*)d_in[22];
    const float* w_exp_fnorm   = (const float*)d_in[23];

    float* vlm = sym(g_vlm);
    float* exq = sym(g_exp);
    float* hv  = sym(g_hv);
    float* he  = sym(g_he);
    float* q   = sym(g_q);
    float* k   = sym(g_k);
    float* v   = sym(g_v);
    float* ke  = sym(g_ke);
    float* ve  = sym(g_ve);
    float* att = sym(g_att);
    float* gg  = sym(g_g);
    float* gu  = sym(g_u);
    float* gge = sym(g_ge);
    float* gue = sym(g_ue);

    cudaMemcpyAsync(vlm, vlm_embeds,    (size_t)PL * TH * sizeof(float),
                    cudaMemcpyDeviceToDevice, s0);
    cudaMemcpyAsync(exq, expert_embeds, (size_t)EL * EH * sizeof(float),
                    cudaMemcpyDeviceToDevice, s0);
    cudaEventRecord(ev0, s0);
    cudaStreamWaitEvent(s2, ev0, 0);

    for (int li = 0; li < LAYERS; li++) {
        if ((li & 1) == 0) {
            // ======== EVEN: joint attention over S=640 ========
            // s2: expert QKV (rows [PL,SS))
            rmsnorm_kernel<<<EL, 256, 0, s2>>>(exq, w_exp_ln1 + (size_t)li * EH, he, EH);
            {
                GemmSegs gs = {};
                gs.s[0] = mkseg(he, w_exp_q      + (size_t)li * EH * (NH * HD),        q + PL * NH * HD,  NH * HD);
                gs.s[1] = mkseg(he, w_exp_k_self + (size_t)(li / 2) * EH * (NKV * HD), k + PL * NKV * HD, NKV * HD);
                gs.s[2] = mkseg(he, w_exp_v_self + (size_t)(li / 2) * EH * (NKV * HD), v + PL * NKV * HD, NKV * HD);
                gemmN(gs, 3, EL, EH, false, s2);
            }
            cudaEventRecord(evA[li], s2);

            // s0: vlm QKV
            if (li > 0) cudaStreamWaitEvent(s0, evX[li - 1], 0);
            rmsnorm_kernel<<<PL, 256, 0, s0>>>(vlm, w_vlm_ln1 + (size_t)li * TH, hv, TH);
            {
                GemmSegs gs = {};
                gs.s[0] = mkseg(hv, w_vlm_q + (size_t)li * TH * (NH * HD),  q, NH * HD);
                gs.s[1] = mkseg(hv, w_vlm_k + (size_t)li * TH * (NKV * HD), k, NKV * HD);
                gs.s[2] = mkseg(hv, w_vlm_v + (size_t)li * TH * (NKV * HD), v, NKV * HD);
                gemmN(gs, 3, PL, TH, false, s0);
            }

            cudaStreamWaitEvent(s0, evA[li], 0);
            {
                int t = SS * NH * 32 + SS * NKV * 32;
                rope_qk_kernel<<<(t + 255) / 256, 256, 0, s0>>>(q, SS, k, SS);
            }
            if (li > 0) cudaStreamWaitEvent(s0, evR[li - 1], 0);
            attn_tile_kernel<<<dim3(SS / 64, NH), 256, ATTN_SMEM, s0>>>(q, k, v, att, SS, PL);
            cudaEventRecord(evB[li], s0);

            // s2: expert block_out
            cudaStreamWaitEvent(s2, evB[li], 0);
            gemm1(att + PL * NH * HD, w_exp_o + (size_t)li * (NH * HD) * EH,
                  exq, EL, EH, NH * HD, true, s2);
            rmsnorm_kernel<<<EL, 256, 0, s2>>>(exq, w_exp_ln2 + (size_t)li * EH, he, EH);
            {
                GemmSegs gs = {};
                gs.s[0] = mkseg(he, w_exp_gate + (size_t)li * EH * EI, gge, EI);
                gs.s[1] = mkseg(he, w_exp_up   + (size_t)li * EH * EI, gue, EI);
                gemmN(gs, 2, EL, EH, false, s2);
            }
            silu_mul_kernel<<<(EL * EI + 255) / 256, 256, 0, s2>>>(gge, gue, gge, EL * EI);
            gemm1(gge, w_exp_down + (size_t)li * EI * EH, exq, EL, EH, EI, true, s2);

            // s0: vlm block_out
            gemm1(att, w_vlm_o + (size_t)li * (NH * HD) * TH, vlm, PL, TH, NH * HD, true, s0);
            rmsnorm_kernel<<<PL, 256, 0, s0>>>(vlm, w_vlm_ln2 + (size_t)li * TH, hv, TH);
            {
                GemmSegs gs = {};
                gs.s[0] = mkseg(hv, w_vlm_gate + (size_t)li * TH * TI, gg, TI);
                gs.s[1] = mkseg(hv, w_vlm_up   + (size_t)li * TH * TI, gu, TI);
                gemmN(gs, 2, PL, TH, false, s0);
            }
            silu_mul_kernel<<<(PL * TI + 255) / 256, 256, 0, s0>>>(gg, gu, gg, PL * TI);
            gemm1(gg, w_vlm_down + (size_t)li * TI * TH, vlm, PL, TH, TI, true, s0);
        } else {
            // ======== ODD: vlm self-attn + expert cross-attn ========
            // s0: vlm QKV + rope (rows [0,PL))
            rmsnorm_kernel<<<PL, 256, 0, s0>>>(vlm, w_vlm_ln1 + (size_t)li * TH, hv, TH);
            {
                GemmSegs gs = {};
                gs.s[0] = mkseg(hv, w_vlm_q + (size_t)li * TH * (NH * HD),  q, NH * HD);
                gs.s[1] = mkseg(hv, w_vlm_k + (size_t)li * TH * (NKV * HD), k, NKV * HD);
                gs.s[2] = mkseg(hv, w_vlm_v + (size_t)li * TH * (NKV * HD), v, NKV * HD);
                gemmN(gs, 3, PL, TH, false, s0);
            }
            {
                int t = PL * NH * 32 + PL * NKV * 32;
                rope_qk_kernel<<<(t + 255) / 256, 256, 0, s0>>>(q, PL, k, PL);
            }
            cudaEventRecord(evK[li], s0);

            // s2: expert q + rope, cross K/V, attn, block_out
            rmsnorm_kernel<<<EL, 256, 0, s2>>>(exq, w_exp_ln1 + (size_t)li * EH, he, EH);
            gemm1(he, w_exp_q + (size_t)li * EH * (NH * HD), q + PL * NH * HD,
                  EL, NH * HD, EH, false, s2);
            { int t = EL * NH * 32; rope_kernel<<<(t + 255) / 256, 256, 0, s2>>>(q + PL * NH * HD, EL, NH, PL); }
            cudaStreamWaitEvent(s2, evK[li], 0);
            {
                GemmSegs gs = {};
                gs.s[0] = mkseg(k, w_exp_k_cross + (size_t)(li / 2) * (NKV * HD) * (NKV * HD), ke, NKV * HD);
                gs.s[1] = mkseg(v, w_exp_v_cross + (size_t)(li / 2) * (NKV * HD) * (NKV * HD), ve, NKV * HD);
                gemmN(gs, 2, PL, NKV * HD, false, s2);
            }
            cudaEventRecord(evX[li], s2);
            attn_tile_kernel<<<dim3(EL / 64, NH), 256, ATTN_SMEM, s2>>>(
                q + PL * NH * HD, ke, ve, att + PL * NH * HD, PL, 0);
            gemm1(att + PL * NH * HD, w_exp_o + (size_t)li * (NH * HD) * EH,
                  exq, EL, EH, NH * HD, true, s2);
            cudaEventRecord(evR[li], s2);
            rmsnorm_kernel<<<EL, 256, 0, s2>>>(exq, w_exp_ln2 + (size_t)li * EH, he, EH);
            {
                GemmSegs gs = {};
                gs.s[0] = mkseg(he, w_exp_gate + (size_t)li * EH * EI, gge, EI);
                gs.s[1] = mkseg(he, w_exp_up   + (size_t)li * EH * EI, gue, EI);
                gemmN(gs, 2, EL, EH, false, s2);
            }
            silu_mul_kernel<<<(EL * EI + 255) / 256, 256, 0, s2>>>(gge, gue, gge, EL * EI);
            gemm1(gge, w_exp_down + (size_t)li * EI * EH, exq, EL, EH, EI, true, s2);
            if (li == LAYERS - 1) cudaEventRecord(evE, s2);

            // s0: vlm attention + block_out
            attn_tile_kernel<<<dim3(PL / 64, NH), 256, ATTN_SMEM, s0>>>(q, k, v, att, PL, 0);
            gemm1(att, w_vlm_o + (size_t)li * (NH * HD) * TH, vlm, PL, TH, NH * HD, true, s0);
            rmsnorm_kernel<<<PL, 256, 0, s0>>>(vlm, w_vlm_ln2 + (size_t)li * TH, hv, TH);
            {
                GemmSegs gs = {};
                gs.s[0] = mkseg(hv, w_vlm_gate + (size_t)li * TH * TI, gg, TI);
                gs.s[1] = mkseg(hv, w_vlm_up   + (size_t)li * TH * TI, gu, TI);
                gemmN(gs, 2, PL, TH, false, s0);
            }
            silu_mul_kernel<<<(PL * TI + 255) / 256, 256, 0, s0>>>(gg, gu, gg, PL * TI);
            gemm1(gg, w_vlm_down + (size_t)li * TI * TH, vlm, PL, TH, TI, true, s0);
        }
    }

    // join expert stream, final norms
    cudaStreamWaitEvent(s0, evE, 0);
    float* out = (float*)d_out;
    rmsnorm_kernel<<<PL, 256, 0, s0>>>(vlm, w_vlm_fnorm, out, TH);
    rmsnorm_kernel<<<EL, 256, 0, s0>>>(exq, w_exp_fnorm, out + (size_t)PL * TH, EH);
}

// round 14
// speedup vs baseline: 3.7264x; 1.0834x over previous
#include <cuda_runtime.h>
#include <cuda_fp16.h>
#include <math.h>
#include <stdint.h>

#define PL 512
#define EL 128
#define SS 640
#define TH 960
#define EH 720
#define TI 2560
#define EI 2048
#define NH 15
#define NKV 5
#define HD 64
#define LAYERS 16

// ---------------- scratch (device globals) ----------------
__device__ __align__(256) float g_vlm[PL * TH];
__device__ __align__(256) float g_exp[EL * EH];
__device__ __align__(256) float g_hv [PL * TH];
__device__ __align__(256) float g_he [EL * EH];
__device__ __align__(256) float g_q  [SS * NH * HD];
__device__ __align__(256) float g_k  [SS * NKV * HD];
__device__ __align__(256) float g_v  [SS * NKV * HD];
__device__ __align__(256) float g_ke [PL * NKV * HD];
__device__ __align__(256) float g_ve [PL * NKV * HD];
__device__ __align__(256) float g_att[SS * NH * HD];
__device__ __align__(256) float g_g  [PL * TI];
__device__ __align__(256) float g_u  [PL * TI];
__device__ __align__(256) float g_ge [EL * EI];
__device__ __align__(256) float g_ue [EL * EI];

// ================= pipelined FP16 tensor-core GEMM =================
// Same loaders / smem layout / schedule as the validated round-4 kernel;
// inner loop now packs fp32 smem values into half2 (k-permuted consistently
// on A and B) and issues m16n8k16 fp16 MMAs with fp32 accumulate.
#define GBK 32
#define ASTRIDE 36
#define BSTRIDE 72
#define AFLOATS (128 * ASTRIDE)
#define BFLOATS (GBK * BSTRIDE)
#define STAGES 3
#define GEMM_SMEM_BYTES (STAGES * (AFLOATS + BFLOATS) * 4)   // 82944

struct GemmSeg { const float* A; const float* B; float* C; int N; int tiles; };
struct GemmSegs { GemmSeg s[3]; };

// pack (lo, hi) floats into one f16x2 register (lo -> low half)
__device__ __forceinline__ uint32_t pack_h2(float lo, float hi) {
    uint32_t r;
    asm("cvt.rn.f16x2.f32 %0, %1, %2;" : "=r"(r) : "f"(hi), "f"(lo));
    return r;
}

__device__ __forceinline__ void cp_async16(uint32_t dst, const float* src, bool valid) {
    int sz = valid ? 16 : 0;
    asm volatile("cp.async.cg.shared.global [%0], [%1], 16, %2;\n"
                 :: "r"(dst), "l"(src), "r"(sz));
}

template <int ACCUM>
__global__ __launch_bounds__(256)
void h16_gemm(GemmSegs segs, int nseg, int M, int K) {
    extern __shared__ float smem_dyn[];

    int bx = blockIdx.x, si = 0;
    while (si + 1 < nseg && bx >= segs.s[si].tiles) { bx -= segs.s[si].tiles; si++; }
    const float* __restrict__ A = segs.s[si].A;
    const float* __restrict__ B = segs.s[si].B;
    float* __restrict__ C = segs.s[si].C;
    const int N  = segs.s[si].N;
    const int n0 = bx * 64;
    const int m0 = blockIdx.y * 128;

    const int tid  = threadIdx.x;
    const int lane = tid & 31;
    const int warp = tid >> 5;
    const int wm   = warp >> 1;
    const int wn   = warp & 1;
    const int gid  = lane >> 2;
    const int tig  = lane & 3;

    const int am = tid >> 2;
    const int ak = (tid & 3) * 8;
    const int bk = tid >> 3;
    const int bn = (tid & 7) * 8;

    const float* aSrc0 = A + (size_t)(m0 + am) * K + ak;
    const float* aSrc1 = A + (size_t)(m0 + am + 64) * K + ak;
    const float* bSrc  = B + (size_t)bk * N + n0 + bn;

    const uint32_t base = (uint32_t)__cvta_generic_to_shared(smem_dyn);
    const uint32_t aD0 = base + (uint32_t)(am * ASTRIDE + ak) * 4u;
    const uint32_t aD1 = base + (uint32_t)((am + 64) * ASTRIDE + ak) * 4u;
    const uint32_t bD  = base + (uint32_t)(STAGES * AFLOATS + bk * BSTRIDE + bn) * 4u;

    const int nk = (K + GBK - 1) / GBK;
    const bool nv0 = (n0 + bn) < N;
    const bool nv1 = (n0 + bn + 4) < N;

    auto issue = [&](int kt) {
        const int st = kt % STAGES;
        const uint32_t aOff = (uint32_t)(st * AFLOATS) * 4u;
        const uint32_t bOff = (uint32_t)(st * BFLOATS) * 4u;
        const int k0 = kt * GBK;
        bool v0 = (k0 + ak) < K;
        bool v1 = (k0 + ak + 4) < K;
        cp_async16(aD0 + aOff,      v0 ? (aSrc0 + k0)     : A, v0);
        cp_async16(aD0 + aOff + 16, v1 ? (aSrc0 + k0 + 4) : A, v1);
        cp_async16(aD1 + aOff,      v0 ? (aSrc1 + k0)     : A, v0);
        cp_async16(aD1 + aOff + 16, v1 ? (aSrc1 + k0 + 4) : A, v1);
        bool kv = (k0 + bk) < K;
        const float* bs = bSrc + (size_t)k0 * N;
        cp_async16(bD + bOff,      (kv && nv0) ? bs       : B, kv && nv0);
        cp_async16(bD + bOff + 16, (kv && nv1) ? (bs + 4) : B, kv && nv1);
        asm volatile("cp.async.commit_group;\n" ::: "memory");
    };

    float c[2][4][4] = {};

    issue(0);
    if (nk > 1) issue(1);
    if (nk > 2) issue(2);

    for (int kt = 0; kt < nk; kt++) {
        int rem = nk - kt - 1;
        if (rem >= 2)      asm volatile("cp.async.wait_group 2;\n" ::: "memory");
        else if (rem == 1) asm volatile("cp.async.wait_group 1;\n" ::: "memory");
        else               asm volatile("cp.async.wait_group 0;\n" ::: "memory");
        __syncthreads();

        const float* as = smem_dyn + (kt % STAGES) * AFLOATS;
        const float* bs = smem_dyn + STAGES * AFLOATS + (kt % STAGES) * BFLOATS;

        // k-permuted fp16 fragments: logical k slot map on BOTH operands is
        // (t, half, pair) -> tig + 4*half + 8*pair, a bijection over [0,16).
#pragma unroll
        for (int ks = 0; ks < GBK; ks += 16) {
            uint32_t a[2][4];
#pragma unroll
            for (int mt = 0; mt < 2; mt++) {
                int mb = wm * 32 + mt * 16;
                const float* r0 = as + (mb + gid    ) * ASTRIDE + ks + tig;
                const float* r1 = as + (mb + gid + 8) * ASTRIDE + ks + tig;
                a[mt][0] = pack_h2(r0[0], r0[4]);
                a[mt][1] = pack_h2(r1[0], r1[4]);
                a[mt][2] = pack_h2(r0[8], r0[12]);
                a[mt][3] = pack_h2(r1[8], r1[12]);
            }
            uint32_t b[4][2];
#pragma unroll
            for (int nt = 0; nt < 4; nt++) {
                int nn = wn * 32 + nt * 8 + gid;
                b[nt][0] = pack_h2(bs[(ks + tig     ) * BSTRIDE + nn],
                                   bs[(ks + tig +  4) * BSTRIDE + nn]);
                b[nt][1] = pack_h2(bs[(ks + tig +  8) * BSTRIDE + nn],
                                   bs[(ks + tig + 12) * BSTRIDE + nn]);
            }
#pragma unroll
            for (int mt = 0; mt < 2; mt++)
#pragma unroll
                for (int nt = 0; nt < 4; nt++) {
                    asm volatile(
                        "mma.sync.aligned.m16n8k16.row.col.f32.f16.f16.f32 "
                        "{%0,%1,%2,%3}, {%4,%5,%6,%7}, {%8,%9}, {%0,%1,%2,%3};"
                        : "+f"(c[mt][nt][0]), "+f"(c[mt][nt][1]),
                          "+f"(c[mt][nt][2]), "+f"(c[mt][nt][3])
                        : "r"(a[mt][0]), "r"(a[mt][1]),
                          "r"(a[mt][2]), "r"(a[mt][3]),
                          "r"(b[nt][0]), "r"(b[nt][1]));
                }
        }
        __syncthreads();
        if (kt + STAGES < nk) issue(kt + STAGES);
    }

#pragma unroll
    for (int mt = 0; mt < 2; mt++) {
#pragma unroll
        for (int nt = 0; nt < 4; nt++) {
            int gm = m0 + wm * 32 + mt * 16 + gid;
            int gn = n0 + wn * 32 + nt * 8 + tig * 2;
            if (gn < N) {
                size_t o0 = (size_t)gm * N + gn;
                size_t o1 = (size_t)(gm + 8) * N + gn;
                if (ACCUM) {
                    C[o0]     += c[mt][nt][0];
                    C[o0 + 1] += c[mt][nt][1];
                    C[o1]     += c[mt][nt][2];
                    C[o1 + 1] += c[mt][nt][3];
                } else {
                    C[o0]     = c[mt][nt][0];
                    C[o0 + 1] = c[mt][nt][1];
                    C[o1]     = c[mt][nt][2];
                    C[o1 + 1] = c[mt][nt][3];
                }
            }
        }
    }
}

static inline GemmSeg mkseg(const float* A, const float* B, float* C, int N) {
    GemmSeg s; s.A = A; s.B = B; s.C = C; s.N = N; s.tiles = (N + 63) / 64;
    return s;
}

static void gemmN(const GemmSegs& gs, int nseg, int M, int K, bool accum,
                  cudaStream_t st) {
    int tiles = 0;
    for (int i = 0; i < nseg; i++) tiles += gs.s[i].tiles;
    dim3 grid(tiles, M / 128);
    if (accum) h16_gemm<1><<<grid, 256, GEMM_SMEM_BYTES, st>>>(gs, nseg, M, K);
    else       h16_gemm<0><<<grid, 256, GEMM_SMEM_BYTES, st>>>(gs, nseg, M, K);
}

static void gemm1(const float* A, const float* B, float* C, int M, int N, int K,
                  bool accum, cudaStream_t st) {
    GemmSegs gs = {};
    gs.s[0] = mkseg(A, B, C, N);
    gemmN(gs, 1, M, K, accum, st);
}

// ---------------- RMSNorm ----------------
__global__ void rmsnorm_kernel(const float* __restrict__ x,
                               const float* __restrict__ w,
                               float* __restrict__ y, int D) {
    const int row = blockIdx.x;
    const float* xr = x + (size_t)row * D;
    float ss = 0.f;
    for (int i = threadIdx.x; i < D; i += 256) { float v = xr[i]; ss += v * v; }
    __shared__ float red[256];
    red[threadIdx.x] = ss;
    __syncthreads();
    for (int s = 128; s > 0; s >>= 1) {
        if (threadIdx.x < s) red[threadIdx.x] += red[threadIdx.x + s];
        __syncthreads();
    }
    float r = rsqrtf(red[0] / (float)D + 1e-5f);
    float* yr = y + (size_t)row * D;
    for (int i = threadIdx.x; i < D; i += 256) yr[i] = w[i] * xr[i] * r;
}

// ---------------- RoPE ----------------
__device__ __forceinline__ void rope_apply(float* x, int r, int h, int d,
                                           int nheads) {
    float pos = (float)r;
    float ts = powf(10000.f, (float)d * (1.f / 32.f));
    float rad = pos / ts;
    float s, c;
    sincosf(rad, &s, &c);
    float* p = x + ((size_t)r * nheads + h) * HD;
    float x1 = p[d], x2 = p[d + 32];
    p[d]      = x1 * c - x2 * s;
    p[d + 32] = x2 * c + x1 * s;
}

__global__ void rope_kernel(float* __restrict__ x, int nrows, int nheads,
                            int pos_base) {
    int idx = blockIdx.x * blockDim.x + threadIdx.x;
    int total = nrows * nheads * 32;
    if (idx >= total) return;
    int d = idx & 31;
    int h = (idx >> 5) % nheads;
    int r = idx / (32 * nheads);
    float pos = (float)(pos_base + r);
    float ts = powf(10000.f, (float)d * (1.f / 32.f));
    float rad = pos / ts;
    float s, c;
    sincosf(rad, &s, &c);
    float* p = x + ((size_t)r * nheads + h) * HD;
    float x1 = p[d], x2 = p[d + 32];
    p[d]      = x1 * c - x2 * s;
    p[d + 32] = x2 * c + x1 * s;
}

__global__ void rope_qk_kernel(float* __restrict__ q, int nq,
                               float* __restrict__ k, int nk2) {
    int idx = blockIdx.x * blockDim.x + threadIdx.x;
    int tq = nq * NH * 32;
    int tk = nk2 * NKV * 32;
    if (idx < tq) {
        int d = idx & 31;
        int h = (idx >> 5) % NH;
        int r = idx / (32 * NH);
        rope_apply(q, r, h, d, NH);
    } else if (idx < tq + tk) {
        int j = idx - tq;
        int d = j & 31;
        int h = (j >> 5) % NKV;
        int r = j / (32 * NKV);
        rope_apply(k, r, h, d, NKV);
    }
}

// ================= tiled flash attention (round-12, validated) =============
#define KPAD 68
#define ATTN_SMEM (3 * 64 * KPAD * 4)   // 52224 bytes

__global__ __launch_bounds__(256)
void attn_tile_kernel(const float* __restrict__ q, const float* __restrict__ k,
                      const float* __restrict__ v, float* __restrict__ out,
                      int nk, int prefix) {
    extern __shared__ float sm[];
    float* ks = sm;
    float* vs = sm + 64 * KPAD;
    float* ps = sm + 2 * 64 * KPAD;

    const int tid = threadIdx.x;
    const int qi  = tid >> 2;
    const int c   = tid & 3;
    const int h   = blockIdx.y;
    const int kvh = h / 3;
    const int q0  = blockIdx.x * 64;
    const int gq  = q0 + qi;

    float4 qreg[16];
    const float4* qrow = (const float4*)(q + ((size_t)gq * NH + h) * HD);
#pragma unroll
    for (int i = 0; i < 16; i++) qreg[i] = qrow[i];

    float o[16];
#pragma unroll
    for (int i = 0; i < 16; i++) o[i] = 0.f;
    float m = -1e30f, l = 0.f;

    const int kmaxq = prefix ? ((gq + 1 > prefix) ? gq + 1 : prefix) : nk;
    const int kend  = prefix ? ((q0 + 64 > prefix) ? q0 + 64 : prefix) : nk;

    const int lrow = tid >> 2;
    const int lcol = (tid & 3) * 16;

    for (int kt = 0; kt < kend; kt += 64) {
        __syncthreads();
        {
            const float4* ksrc = (const float4*)(k + ((size_t)(kt + lrow) * NKV + kvh) * HD + lcol);
            const float4* vsrc = (const float4*)(v + ((size_t)(kt + lrow) * NKV + kvh) * HD + lcol);
            float4* kdst = (float4*)(ks + lrow * KPAD + lcol);
            float4* vdst = (float4*)(vs + lrow * KPAD + lcol);
#pragma unroll
            for (int i = 0; i < 4; i++) kdst[i] = ksrc[i];
#pragma unroll
            for (int i = 0; i < 4; i++) vdst[i] = vsrc[i];
        }
        __syncthreads();

        float s[16];
        float tmax = -1e30f;
#pragma unroll
        for (int jj = 0; jj < 16; jj++) {
            int j = 4 * jj + c;
            const float4* krow = (const float4*)(ks + j * KPAD);
            float dot = 0.f;
#pragma unroll
            for (int t = 0; t < 16; t++) {
                float4 kk = krow[t];
                dot += qreg[t].x * kk.x + qreg[t].y * kk.y
                     + qreg[t].z * kk.z + qreg[t].w * kk.w;
            }
            dot *= 0.125f;
            if (kt + j >= kmaxq) dot = -1e30f;
            s[jj] = dot;
            tmax = fmaxf(tmax, dot);
        }
        tmax = fmaxf(tmax, __shfl_xor_sync(0xffffffffu, tmax, 1));
        tmax = fmaxf(tmax, __shfl_xor_sync(0xffffffffu, tmax, 2));
        float mnew  = fmaxf(m, tmax);
        float scale = expf(m - mnew);

        float psum = 0.f;
#pragma unroll
        for (int jj = 0; jj < 16; jj++) {
            float e = expf(s[jj] - mnew);
            ps[qi * KPAD + 4 * jj + c] = e;
            psum += e;
        }
        psum += __shfl_xor_sync(0xffffffffu, psum, 1);
        psum += __shfl_xor_sync(0xffffffffu, psum, 2);
        l = l * scale + psum;
#pragma unroll
        for (int i = 0; i < 16; i++) o[i] *= scale;
        m = mnew;
        __syncthreads();

#pragma unroll 16
        for (int j = 0; j < 64; j++) {
            float p = ps[qi * KPAD + j];
            const float4* vrow = (const float4*)(vs + j * KPAD + c * 16);
#pragma unroll
            for (int t = 0; t < 4; t++) {
                float4 vv = vrow[t];
                o[4 * t + 0] += p * vv.x;
                o[4 * t + 1] += p * vv.y;
                o[4 * t + 2] += p * vv.z;
                o[4 * t + 3] += p * vv.w;
            }
        }
    }

    float inv = 1.f / l;
    float* orow = out + ((size_t)gq * NH + h) * HD + c * 16;
#pragma unroll
    for (int i = 0; i < 16; i++) orow[i] = o[i] * inv;
}

// ---------------- silu(g) * u ----------------
__global__ void silu_mul_kernel(const float* __restrict__ g,
                                const float* __restrict__ u,
                                float* __restrict__ m, int n) {
    int i = blockIdx.x * blockDim.x + threadIdx.x;
    if (i < n) {
        float x = g[i];
        float s = x / (1.f + expf(-x));
        m[i] = s * u[i];
    }
}

// ---------------- launch ----------------
static float* sym(const void* s) {
    void* p = nullptr;
    cudaGetSymbolAddress(&p, s);
    return (float*)p;
}

static cudaStream_t s2;
static cudaEvent_t ev0, evA[LAYERS], evB[LAYERS], evK[LAYERS],
                   evX[LAYERS], evR[LAYERS], evE;
static bool g_inited = false;

static void init_once() {
    if (g_inited) return;
    cudaStreamCreateWithFlags(&s2, cudaStreamNonBlocking);
    cudaEventCreateWithFlags(&ev0, cudaEventDisableTiming);
    cudaEventCreateWithFlags(&evE, cudaEventDisableTiming);
    for (int i = 0; i < LAYERS; i++) {
        cudaEventCreateWithFlags(&evA[i], cudaEventDisableTiming);
        cudaEventCreateWithFlags(&evB[i], cudaEventDisableTiming);
        cudaEventCreateWithFlags(&evK[i], cudaEventDisableTiming);
        cudaEventCreateWithFlags(&evX[i], cudaEventDisableTiming);
        cudaEventCreateWithFlags(&evR[i], cudaEventDisableTiming);
    }
    cudaFuncSetAttribute(h16_gemm<0>, cudaFuncAttributeMaxDynamicSharedMemorySize, GEMM_SMEM_BYTES);
    cudaFuncSetAttribute(h16_gemm<1>, cudaFuncAttributeMaxDynamicSharedMemorySize, GEMM_SMEM_BYTES);
    cudaFuncSetAttribute(attn_tile_kernel, cudaFuncAttributeMaxDynamicSharedMemorySize, ATTN_SMEM);
    g_inited = true;
}

extern "C" void kernel_launch(void* const* d_in, const int* in_sizes, int n_in,
                              void* d_out, int out_size) {
    init_once();
    cudaStream_t s0 = 0;

    const float* vlm_embeds    = (const float*)d_in[0];
    const float* expert_embeds = (const float*)d_in[1];
    const float* w_vlm_q       = (const float*)d_in[2];
    const float* w_vlm_k       = (const float*)d_in[3];
    const float* w_vlm_v       = (const float*)d_in[4];
    const float* w_vlm_o       = (const float*)d_in[5];
    const float* w_vlm_ln1     = (const float*)d_in[6];
    const float* w_vlm_ln2     = (const float*)d_in[7];
    const float* w_vlm_gate    = (const float*)d_in[8];
    const float* w_vlm_up      = (const float*)d_in[9];
    const float* w_vlm_down    = (const float*)d_in[10];
    const float* w_vlm_fnorm   = (const float*)d_in[11];
    const float* w_exp_q       = (const float*)d_in[12];
    const float* w_exp_k_self  = (const float*)d_in[13];
    const float* w_exp_v_self  = (const float*)d_in[14];
    const float* w_exp_k_cross = (const float*)d_in[15];
    const float* w_exp_v_cross = (const float*)d_in[16];
    const float* w_exp_o       = (const float*)d_in[17];
    const float* w_exp_ln1     = (const float*)d_in[18];
    const float* w_exp_ln2     = (const float*)d_in[19];
    const float* w_exp_gate    = (const float*)d_in[20];
    const float* w_exp_up      = (const float*)d_in[21];
    const float* w_exp_down    = (const float*)d_in[22];
    const float* w_exp_fnorm   = (const float*)d_in[23];

    float* vlm = sym(g_vlm);
    float* exq = sym(g_exp);
    float* hv  = sym(g_hv);
    float* he  = sym(g_he);
    float* q   = sym(g_q);
    float* k   = sym(g_k);
    float* v   = sym(g_v);
    float* ke  = sym(g_ke);
    float* ve  = sym(g_ve);
    float* att = sym(g_att);
    float* gg  = sym(g_g);
    float* gu  = sym(g_u);
    float* gge = sym(g_ge);
    float* gue = sym(g_ue);

    cudaMemcpyAsync(vlm, vlm_embeds,    (size_t)PL * TH * sizeof(float),
                    cudaMemcpyDeviceToDevice, s0);
    cudaMemcpyAsync(exq, expert_embeds, (size_t)EL * EH * sizeof(float),
                    cudaMemcpyDeviceToDevice, s0);
    cudaEventRecord(ev0, s0);
    cudaStreamWaitEvent(s2, ev0, 0);

    for (int li = 0; li < LAYERS; li++) {
        if ((li & 1) == 0) {
            // ======== EVEN: joint attention over S=640 ========
            rmsnorm_kernel<<<EL, 256, 0, s2>>>(exq, w_exp_ln1 + (size_t)li * EH, he, EH);
            {
                GemmSegs gs = {};
                gs.s[0] = mkseg(he, w_exp_q      + (size_t)li * EH * (NH * HD),        q + PL * NH * HD,  NH * HD);
                gs.s[1] = mkseg(he, w_exp_k_self + (size_t)(li / 2) * EH * (NKV * HD), k + PL * NKV * HD, NKV * HD);
                gs.s[2] = mkseg(he, w_exp_v_self + (size_t)(li / 2) * EH * (NKV * HD), v + PL * NKV * HD, NKV * HD);
                gemmN(gs, 3, EL, EH, false, s2);
            }
            cudaEventRecord(evA[li], s2);

            if (li > 0) cudaStreamWaitEvent(s0, evX[li - 1], 0);
            rmsnorm_kernel<<<PL, 256, 0, s0>>>(vlm, w_vlm_ln1 + (size_t)li * TH, hv, TH);
            {
                GemmSegs gs = {};
                gs.s[0] = mkseg(hv, w_vlm_q + (size_t)li * TH * (NH * HD),  q, NH * HD);
                gs.s[1] = mkseg(hv, w_vlm_k + (size_t)li * TH * (NKV * HD), k, NKV * HD);
                gs.s[2] = mkseg(hv, w_vlm_v + (size_t)li * TH * (NKV * HD), v, NKV * HD);
                gemmN(gs, 3, PL, TH, false, s0);
            }

            cudaStreamWaitEvent(s0, evA[li], 0);
            {
                int t = SS * NH * 32 + SS * NKV * 32;
                rope_qk_kernel<<<(t + 255) / 256, 256, 0, s0>>>(q, SS, k, SS);
            }
            if (li > 0) cudaStreamWaitEvent(s0, evR[li - 1], 0);
            attn_tile_kernel<<<dim3(SS / 64, NH), 256, ATTN_SMEM, s0>>>(q, k, v, att, SS, PL);
            cudaEventRecord(evB[li], s0);

            cudaStreamWaitEvent(s2, evB[li], 0);
            gemm1(att + PL * NH * HD, w_exp_o + (size_t)li * (NH * HD) * EH,
                  exq, EL, EH, NH * HD, true, s2);
            rmsnorm_kernel<<<EL, 256, 0, s2>>>(exq, w_exp_ln2 + (size_t)li * EH, he, EH);
            {
                GemmSegs gs = {};
                gs.s[0] = mkseg(he, w_exp_gate + (size_t)li * EH * EI, gge, EI);
                gs.s[1] = mkseg(he, w_exp_up   + (size_t)li * EH * EI, gue, EI);
                gemmN(gs, 2, EL, EH, false, s2);
            }
            silu_mul_kernel<<<(EL * EI + 255) / 256, 256, 0, s2>>>(gge, gue, gge, EL * EI);
            gemm1(gge, w_exp_down + (size_t)li * EI * EH, exq, EL, EH, EI, true, s2);

            gemm1(att, w_vlm_o + (size_t)li * (NH * HD) * TH, vlm, PL, TH, NH * HD, true, s0);
            rmsnorm_kernel<<<PL, 256, 0, s0>>>(vlm, w_vlm_ln2 + (size_t)li * TH, hv, TH);
            {
                GemmSegs gs = {};
                gs.s[0] = mkseg(hv, w_vlm_gate + (size_t)li * TH * TI, gg, TI);
                gs.s[1] = mkseg(hv, w_vlm_up   + (size_t)li * TH * TI, gu, TI);
                gemmN(gs, 2, PL, TH, false, s0);
            }
            silu_mul_kernel<<<(PL * TI + 255) / 256, 256, 0, s0>>>(gg, gu, gg, PL * TI);
            gemm1(gg, w_vlm_down + (size_t)li * TI * TH, vlm, PL, TH, TI, true, s0);
        } else {
            // ======== ODD: vlm self-attn + expert cross-attn ========
            rmsnorm_kernel<<<PL, 256, 0, s0>>>(vlm, w_vlm_ln1 + (size_t)li * TH, hv, TH);
            {
                GemmSegs gs = {};
                gs.s[0] = mkseg(hv, w_vlm_q + (size_t)li * TH * (NH * HD),  q, NH * HD);
                gs.s[1] = mkseg(hv, w_vlm_k + (size_t)li * TH * (NKV * HD), k, NKV * HD);
                gs.s[2] = mkseg(hv, w_vlm_v + (size_t)li * TH * (NKV * HD), v, NKV * HD);
                gemmN(gs, 3, PL, TH, false, s0);
            }
            {
                int t = PL * NH * 32 + PL * NKV * 32;
                rope_qk_kernel<<<(t + 255) / 256, 256, 0, s0>>>(q, PL, k, PL);
            }
            cudaEventRecord(evK[li], s0);

            rmsnorm_kernel<<<EL, 256, 0, s2>>>(exq, w_exp_ln1 + (size_t)li * EH, he, EH);
            gemm1(he, w_exp_q + (size_t)li * EH * (NH * HD), q + PL * NH * HD,
                  EL, NH * HD, EH, false, s2);
            { int t = EL * NH * 32; rope_kernel<<<(t + 255) / 256, 256, 0, s2>>>(q + PL * NH * HD, EL, NH, PL); }
            cudaStreamWaitEvent(s2, evK[li], 0);
            {
                GemmSegs gs = {};
                gs.s[0] = mkseg(k, w_exp_k_cross + (size_t)(li / 2) * (NKV * HD) * (NKV * HD), ke, NKV * HD);
                gs.s[1] = mkseg(v, w_exp_v_cross + (size_t)(li / 2) * (NKV * HD) * (NKV * HD), ve, NKV * HD);
                gemmN(gs, 2, PL, NKV * HD, false, s2);
            }
            cudaEventRecord(evX[li], s2);
            attn_tile_kernel<<<dim3(EL / 64, NH), 256, ATTN_SMEM, s2>>>(
                q + PL * NH * HD, ke, ve, att + PL * NH * HD, PL, 0);
            gemm1(att + PL * NH * HD, w_exp_o + (size_t)li * (NH * HD) * EH,
                  exq, EL, EH, NH * HD, true, s2);
            cudaEventRecord(evR[li], s2);
            rmsnorm_kernel<<<EL, 256, 0, s2>>>(exq, w_exp_ln2 + (size_t)li * EH, he, EH);
            {
                GemmSegs gs = {};
                gs.s[0] = mkseg(he, w_exp_gate + (size_t)li * EH * EI, gge, EI);
                gs.s[1] = mkseg(he, w_exp_up   + (size_t)li * EH * EI, gue, EI);
                gemmN(gs, 2, EL, EH, false, s2);
            }
            silu_mul_kernel<<<(EL * EI + 255) / 256, 256, 0, s2>>>(gge, gue, gge, EL * EI);
            gemm1(gge, w_exp_down + (size_t)li * EI * EH, exq, EL, EH, EI, true, s2);
            if (li == LAYERS - 1) cudaEventRecord(evE, s2);

            attn_tile_kernel<<<dim3(PL / 64, NH), 256, ATTN_SMEM, s0>>>(q, k, v, att, PL, 0);
            gemm1(att, w_vlm_o + (size_t)li * (NH * HD) * TH, vlm, PL, TH, NH * HD, true, s0);
            rmsnorm_kernel<<<PL, 256, 0, s0>>>(vlm, w_vlm_ln2 + (size_t)li * TH, hv, TH);
            {
                GemmSegs gs = {};
                gs.s[0] = mkseg(hv, w_vlm_gate + (size_t)li * TH * TI, gg, TI);
                gs.s[1] = mkseg(hv, w_vlm_up   + (size_t)li * TH * TI, gu, TI);
                gemmN(gs, 2, PL, TH, false, s0);
            }
            silu_mul_kernel<<<(PL * TI + 255) / 256, 256, 0, s0>>>(gg, gu, gg, PL * TI);
            gemm1(gg, w_vlm_down + (size_t)li * TI * TH, vlm, PL, TH, TI, true, s0);
        }
    }

    cudaStreamWaitEvent(s0, evE, 0);
    float* out = (float*)d_out;
    rmsnorm_kernel<<<PL, 256, 0, s0>>>(vlm, w_vlm_fnorm, out, TH);
    rmsnorm_kernel<<<EL, 256, 0, s0>>>(exq, w_exp_fnorm, out + (size_t)PL * TH, EH);
}

// round 15
// speedup vs baseline: 4.3012x; 1.1543x over previous
#include <cuda_runtime.h>
#include <cuda_fp16.h>
#include <math.h>
#include <stdint.h>

#define PL 512
#define EL 128
#define SS 640
#define TH 960
#define EH 720
#define TI 2560
#define EI 2048
#define NH 15
#define NKV 5
#define HD 64
#define LAYERS 16

// ---------------- scratch (device globals) ----------------
__device__ __align__(256) float g_vlm[PL * TH];
__device__ __align__(256) float g_exp[EL * EH];
__device__ __align__(256) float g_hv [PL * TH];
__device__ __align__(256) float g_he [EL * EH];
__device__ __align__(256) float g_q  [SS * NH * HD];
__device__ __align__(256) float g_k  [SS * NKV * HD];
__device__ __align__(256) float g_v  [SS * NKV * HD];
__device__ __align__(256) float g_ke [PL * NKV * HD];
__device__ __align__(256) float g_ve [PL * NKV * HD];
__device__ __align__(256) float g_att[SS * NH * HD];
__device__ __align__(256) float g_g  [PL * TI];
__device__ __align__(256) float g_u  [PL * TI];
__device__ __align__(256) float g_ge [EL * EI];
__device__ __align__(256) float g_ue [EL * EI];
__device__ __align__(256) float g_p0 [PL * TH];   // split-K partial, stream 0
__device__ __align__(256) float g_p2 [EL * EH];   // split-K partial, stream 2

// ================= pipelined FP16 tensor-core GEMM (+ split-K) =============
// Validated round-14 design; adds a K-window per blockIdx.z:
//   z=0: C over K[0,kchunk) with ACCUM semantics
//   z>0: partial buffer over K[z*kchunk, ...), plain store
// followed by a deterministic add kernel.
#define GBK 32
#define ASTRIDE 36
#define BSTRIDE 72
#define AFLOATS (128 * ASTRIDE)
#define BFLOATS (GBK * BSTRIDE)
#define STAGES 3
#define GEMM_SMEM_BYTES (STAGES * (AFLOATS + BFLOATS) * 4)   // 82944

struct GemmSeg { const float* A; const float* B; float* C; int N; int tiles; };
struct GemmSegs { GemmSeg s[3]; };

__device__ __forceinline__ uint32_t pack_h2(float lo, float hi) {
    uint32_t r;
    asm("cvt.rn.f16x2.f32 %0, %1, %2;" : "=r"(r) : "f"(hi), "f"(lo));
    return r;
}

__device__ __forceinline__ void cp_async16(uint32_t dst, const float* src, bool valid) {
    int sz = valid ? 16 : 0;
    asm volatile("cp.async.cg.shared.global [%0], [%1], 16, %2;\n"
                 :: "r"(dst), "l"(src), "r"(sz));
}

template <int ACCUM>
__global__ __launch_bounds__(256)
void h16_gemm(GemmSegs segs, int nseg, int M, int K, int kchunk, float* part) {
    extern __shared__ float smem_dyn[];

    int bx = blockIdx.x, si = 0;
    while (si + 1 < nseg && bx >= segs.s[si].tiles) { bx -= segs.s[si].tiles; si++; }
    const float* __restrict__ A = segs.s[si].A;
    const float* __restrict__ B = segs.s[si].B;
    float* __restrict__ C = segs.s[si].C;
    const int N  = segs.s[si].N;
    const int n0 = bx * 64;
    const int m0 = blockIdx.y * 128;

    const int z     = blockIdx.z;
    const int kbase = z * kchunk;
    const int kend  = (kbase + kchunk < K) ? (kbase + kchunk) : K;
    const bool acc  = ACCUM && (z == 0);
    if (z > 0) C = part;          // split partial (single-seg use only)

    const int tid  = threadIdx.x;
    const int lane = tid & 31;
    const int warp = tid >> 5;
    const int wm   = warp >> 1;
    const int wn   = warp & 1;
    const int gid  = lane >> 2;
    const int tig  = lane & 3;

    const int am = tid >> 2;
    const int ak = (tid & 3) * 8;
    const int bk = tid >> 3;
    const int bn = (tid & 7) * 8;

    const float* aSrc0 = A + (size_t)(m0 + am) * K + ak;
    const float* aSrc1 = A + (size_t)(m0 + am + 64) * K + ak;
    const float* bSrc  = B + (size_t)bk * N + n0 + bn;

    const uint32_t base = (uint32_t)__cvta_generic_to_shared(smem_dyn);
    const uint32_t aD0 = base + (uint32_t)(am * ASTRIDE + ak) * 4u;
    const uint32_t aD1 = base + (uint32_t)((am + 64) * ASTRIDE + ak) * 4u;
    const uint32_t bD  = base + (uint32_t)(STAGES * AFLOATS + bk * BSTRIDE + bn) * 4u;

    const int nk = (kend - kbase + GBK - 1) / GBK;
    const bool nv0 = (n0 + bn) < N;
    const bool nv1 = (n0 + bn + 4) < N;

    auto issue = [&](int kt) {
        const int st = kt % STAGES;
        const uint32_t aOff = (uint32_t)(st * AFLOATS) * 4u;
        const uint32_t bOff = (uint32_t)(st * BFLOATS) * 4u;
        const int k0 = kbase + kt * GBK;
        bool v0 = (k0 + ak) < kend;
        bool v1 = (k0 + ak + 4) < kend;
        cp_async16(aD0 + aOff,      v0 ? (aSrc0 + k0)     : A, v0);
        cp_async16(aD0 + aOff + 16, v1 ? (aSrc0 + k0 + 4) : A, v1);
        cp_async16(aD1 + aOff,      v0 ? (aSrc1 + k0)     : A, v0);
        cp_async16(aD1 + aOff + 16, v1 ? (aSrc1 + k0 + 4) : A, v1);
        bool kv = (k0 + bk) < kend;
        const float* bs = bSrc + (size_t)k0 * N;
        cp_async16(bD + bOff,      (kv && nv0) ? bs       : B, kv && nv0);
        cp_async16(bD + bOff + 16, (kv && nv1) ? (bs + 4) : B, kv && nv1);
        asm volatile("cp.async.commit_group;\n" ::: "memory");
    };

    float c[2][4][4] = {};

    issue(0);
    if (nk > 1) issue(1);
    if (nk > 2) issue(2);

    for (int kt = 0; kt < nk; kt++) {
        int rem = nk - kt - 1;
        if (rem >= 2)      asm volatile("cp.async.wait_group 2;\n" ::: "memory");
        else if (rem == 1) asm volatile("cp.async.wait_group 1;\n" ::: "memory");
        else               asm volatile("cp.async.wait_group 0;\n" ::: "memory");
        __syncthreads();

        const float* as = smem_dyn + (kt % STAGES) * AFLOATS;
        const float* bs = smem_dyn + STAGES * AFLOATS + (kt % STAGES) * BFLOATS;

#pragma unroll
        for (int ks = 0; ks < GBK; ks += 16) {
            uint32_t a[2][4];
#pragma unroll
            for (int mt = 0; mt < 2; mt++) {
                int mb = wm * 32 + mt * 16;
                const float* r0 = as + (mb + gid    ) * ASTRIDE + ks + tig;
                const float* r1 = as + (mb + gid + 8) * ASTRIDE + ks + tig;
                a[mt][0] = pack_h2(r0[0], r0[4]);
                a[mt][1] = pack_h2(r1[0], r1[4]);
                a[mt][2] = pack_h2(r0[8], r0[12]);
                a[mt][3] = pack_h2(r1[8], r1[12]);
            }
            uint32_t b[4][2];
#pragma unroll
            for (int nt = 0; nt < 4; nt++) {
                int nn = wn * 32 + nt * 8 + gid;
                b[nt][0] = pack_h2(bs[(ks + tig     ) * BSTRIDE + nn],
                                   bs[(ks + tig +  4) * BSTRIDE + nn]);
                b[nt][1] = pack_h2(bs[(ks + tig +  8) * BSTRIDE + nn],
                                   bs[(ks + tig + 12) * BSTRIDE + nn]);
            }
#pragma unroll
            for (int mt = 0; mt < 2; mt++)
#pragma unroll
                for (int nt = 0; nt < 4; nt++) {
                    asm volatile(
                        "mma.sync.aligned.m16n8k16.row.col.f32.f16.f16.f32 "
                        "{%0,%1,%2,%3}, {%4,%5,%6,%7}, {%8,%9}, {%0,%1,%2,%3};"
                        : "+f"(c[mt][nt][0]), "+f"(c[mt][nt][1]),
                          "+f"(c[mt][nt][2]), "+f"(c[mt][nt][3])
                        : "r"(a[mt][0]), "r"(a[mt][1]),
                          "r"(a[mt][2]), "r"(a[mt][3]),
                          "r"(b[nt][0]), "r"(b[nt][1]));
                }
        }
        __syncthreads();
        if (kt + STAGES < nk) issue(kt + STAGES);
    }

#pragma unroll
    for (int mt = 0; mt < 2; mt++) {
#pragma unroll
        for (int nt = 0; nt < 4; nt++) {
            int gm = m0 + wm * 32 + mt * 16 + gid;
            int gn = n0 + wn * 32 + nt * 8 + tig * 2;
            if (gn < N) {
                size_t o0 = (size_t)gm * N + gn;
                size_t o1 = (size_t)(gm + 8) * N + gn;
                if (acc) {
                    C[o0]     += c[mt][nt][0];
                    C[o0 + 1] += c[mt][nt][1];
                    C[o1]     += c[mt][nt][2];
                    C[o1 + 1] += c[mt][nt][3];
                } else {
                    C[o0]     = c[mt][nt][0];
                    C[o0 + 1] = c[mt][nt][1];
                    C[o1]     = c[mt][nt][2];
                    C[o1 + 1] = c[mt][nt][3];
                }
            }
        }
    }
}

// deterministic split-K fold: C[i] += P[i]
__global__ void addp_kernel(float* __restrict__ C, const float* __restrict__ P,
                            int n) {
    int i = blockIdx.x * blockDim.x + threadIdx.x;
    if (i < n) C[i] += P[i];
}

static inline GemmSeg mkseg(const float* A, const float* B, float* C, int N) {
    GemmSeg s; s.A = A; s.B = B; s.C = C; s.N = N; s.tiles = (N + 63) / 64;
    return s;
}

static void gemmN(const GemmSegs& gs, int nseg, int M, int K, bool accum,
                  cudaStream_t st) {
    int tiles = 0;
    for (int i = 0; i < nseg; i++) tiles += gs.s[i].tiles;
    dim3 grid(tiles, M / 128, 1);
    if (accum) h16_gemm<1><<<grid, 256, GEMM_SMEM_BYTES, st>>>(gs, nseg, M, K, K, nullptr);
    else       h16_gemm<0><<<grid, 256, GEMM_SMEM_BYTES, st>>>(gs, nseg, M, K, K, nullptr);
}

static void gemm1(const float* A, const float* B, float* C, int M, int N, int K,
                  bool accum, cudaStream_t st) {
    GemmSegs gs = {};
    gs.s[0] = mkseg(A, B, C, N);
    gemmN(gs, 1, M, K, accum, st);
}

// split-K=2 accumulate GEMM: C += A@B via two K-halves + deterministic fold
static void gemmSplit(const float* A, const float* B, float* C, float* part,
                      int M, int N, int K, cudaStream_t st) {
    GemmSegs gs = {};
    gs.s[0] = mkseg(A, B, C, N);
    dim3 grid(gs.s[0].tiles, M / 128, 2);
    h16_gemm<1><<<grid, 256, GEMM_SMEM_BYTES, st>>>(gs, 1, M, K, K / 2, part);
    int n = M * N;
    addp_kernel<<<(n + 511) / 512, 512, 0, st>>>(C, part, n);
}

// ---------------- RMSNorm ----------------
__global__ void rmsnorm_kernel(const float* __restrict__ x,
                               const float* __restrict__ w,
                               float* __restrict__ y, int D) {
    const int row = blockIdx.x;
    const float* xr = x + (size_t)row * D;
    float ss = 0.f;
    for (int i = threadIdx.x; i < D; i += 256) { float v = xr[i]; ss += v * v; }
    __shared__ float red[256];
    red[threadIdx.x] = ss;
    __syncthreads();
    for (int s = 128; s > 0; s >>= 1) {
        if (threadIdx.x < s) red[threadIdx.x] += red[threadIdx.x + s];
        __syncthreads();
    }
    float r = rsqrtf(red[0] / (float)D + 1e-5f);
    float* yr = y + (size_t)row * D;
    for (int i = threadIdx.x; i < D; i += 256) yr[i] = w[i] * xr[i] * r;
}

// ---------------- RoPE ----------------
__device__ __forceinline__ void rope_apply(float* x, int r, int h, int d,
                                           int nheads) {
    float pos = (float)r;
    float ts = powf(10000.f, (float)d * (1.f / 32.f));
    float rad = pos / ts;
    float s, c;
    sincosf(rad, &s, &c);
    float* p = x + ((size_t)r * nheads + h) * HD;
    float x1 = p[d], x2 = p[d + 32];
    p[d]      = x1 * c - x2 * s;
    p[d + 32] = x2 * c + x1 * s;
}

__global__ void rope_kernel(float* __restrict__ x, int nrows, int nheads,
                            int pos_base) {
    int idx = blockIdx.x * blockDim.x + threadIdx.x;
    int total = nrows * nheads * 32;
    if (idx >= total) return;
    int d = idx & 31;
    int h = (idx >> 5) % nheads;
    int r = idx / (32 * nheads);
    float pos = (float)(pos_base + r);
    float ts = powf(10000.f, (float)d * (1.f / 32.f));
    float rad = pos / ts;
    float s, c;
    sincosf(rad, &s, &c);
    float* p = x + ((size_t)r * nheads + h) * HD;
    float x1 = p[d], x2 = p[d + 32];
    p[d]      = x1 * c - x2 * s;
    p[d + 32] = x2 * c + x1 * s;
}

__global__ void rope_qk_kernel(float* __restrict__ q, int nq,
                               float* __restrict__ k, int nk2) {
    int idx = blockIdx.x * blockDim.x + threadIdx.x;
    int tq = nq * NH * 32;
    int tk = nk2 * NKV * 32;
    if (idx < tq) {
        int d = idx & 31;
        int h = (idx >> 5) % NH;
        int r = idx / (32 * NH);
        rope_apply(q, r, h, d, NH);
    } else if (idx < tq + tk) {
        int j = idx - tq;
        int d = j & 31;
        int h = (j >> 5) % NKV;
        int r = j / (32 * NKV);
        rope_apply(k, r, h, d, NKV);
    }
}

// ================= tiled flash attention (round-12, validated) =============
#define KPAD 68
#define ATTN_SMEM (3 * 64 * KPAD * 4)   // 52224 bytes

__global__ __launch_bounds__(256)
void attn_tile_kernel(const float* __restrict__ q, const float* __restrict__ k,
                      const float* __restrict__ v, float* __restrict__ out,
                      int nk, int prefix) {
    extern __shared__ float sm[];
    float* ks = sm;
    float* vs = sm + 64 * KPAD;
    float* ps = sm + 2 * 64 * KPAD;

    const int tid = threadIdx.x;
    const int qi  = tid >> 2;
    const int c   = tid & 3;
    const int h   = blockIdx.y;
    const int kvh = h / 3;
    const int q0  = blockIdx.x * 64;
    const int gq  = q0 + qi;

    float4 qreg[16];
    const float4* qrow = (const float4*)(q + ((size_t)gq * NH + h) * HD);
#pragma unroll
    for (int i = 0; i < 16; i++) qreg[i] = qrow[i];

    float o[16];
#pragma unroll
    for (int i = 0; i < 16; i++) o[i] = 0.f;
    float m = -1e30f, l = 0.f;

    const int kmaxq = prefix ? ((gq + 1 > prefix) ? gq + 1 : prefix) : nk;
    const int kend  = prefix ? ((q0 + 64 > prefix) ? q0 + 64 : prefix) : nk;

    const int lrow = tid >> 2;
    const int lcol = (tid & 3) * 16;

    for (int kt = 0; kt < kend; kt += 64) {
        __syncthreads();
        {
            const float4* ksrc = (const float4*)(k + ((size_t)(kt + lrow) * NKV + kvh) * HD + lcol);
            const float4* vsrc = (const float4*)(v + ((size_t)(kt + lrow) * NKV + kvh) * HD + lcol);
            float4* kdst = (float4*)(ks + lrow * KPAD + lcol);
            float4* vdst = (float4*)(vs + lrow * KPAD + lcol);
#pragma unroll
            for (int i = 0; i < 4; i++) kdst[i] = ksrc[i];
#pragma unroll
            for (int i = 0; i < 4; i++) vdst[i] = vsrc[i];
        }
        __syncthreads();

        float s[16];
        float tmax = -1e30f;
#pragma unroll
        for (int jj = 0; jj < 16; jj++) {
            int j = 4 * jj + c;
            const float4* krow = (const float4*)(ks + j * KPAD);
            float dot = 0.f;
#pragma unroll
            for (int t = 0; t < 16; t++) {
                float4 kk = krow[t];
                dot += qreg[t].x * kk.x + qreg[t].y * kk.y
                     + qreg[t].z * kk.z + qreg[t].w * kk.w;
            }
            dot *= 0.125f;
            if (kt + j >= kmaxq) dot = -1e30f;
            s[jj] = dot;
            tmax = fmaxf(tmax, dot);
        }
        tmax = fmaxf(tmax, __shfl_xor_sync(0xffffffffu, tmax, 1));
        tmax = fmaxf(tmax, __shfl_xor_sync(0xffffffffu, tmax, 2));
        float mnew  = fmaxf(m, tmax);
        float scale = expf(m - mnew);

        float psum = 0.f;
#pragma unroll
        for (int jj = 0; jj < 16; jj++) {
            float e = expf(s[jj] - mnew);
            ps[qi * KPAD + 4 * jj + c] = e;
            psum += e;
        }
        psum += __shfl_xor_sync(0xffffffffu, psum, 1);
        psum += __shfl_xor_sync(0xffffffffu, psum, 2);
        l = l * scale + psum;
#pragma unroll
        for (int i = 0; i < 16; i++) o[i] *= scale;
        m = mnew;
        __syncthreads();

#pragma unroll 16
        for (int j = 0; j < 64; j++) {
            float p = ps[qi * KPAD + j];
            const float4* vrow = (const float4*)(vs + j * KPAD + c * 16);
#pragma unroll
            for (int t = 0; t < 4; t++) {
                float4 vv = vrow[t];
                o[4 * t + 0] += p * vv.x;
                o[4 * t + 1] += p * vv.y;
                o[4 * t + 2] += p * vv.z;
                o[4 * t + 3] += p * vv.w;
            }
        }
    }

    float inv = 1.f / l;
    float* orow = out + ((size_t)gq * NH + h) * HD + c * 16;
#pragma unroll
    for (int i = 0; i < 16; i++) orow[i] = o[i] * inv;
}

// ---------------- silu(g) * u ----------------
__global__ void silu_mul_kernel(const float* __restrict__ g,
                                const float* __restrict__ u,
                                float* __restrict__ m, int n) {
    int i = blockIdx.x * blockDim.x + threadIdx.x;
    if (i < n) {
        float x = g[i];
        float s = x / (1.f + expf(-x));
        m[i] = s * u[i];
    }
}

// ---------------- launch ----------------
static float* sym(const void* s) {
    void* p = nullptr;
    cudaGetSymbolAddress(&p, s);
    return (float*)p;
}

static cudaStream_t s2;
static cudaEvent_t ev0, evA[LAYERS], evB[LAYERS], evK[LAYERS],
                   evX[LAYERS], evR[LAYERS], evE;
static bool g_inited = false;

static void init_once() {
    if (g_inited) return;
    cudaStreamCreateWithFlags(&s2, cudaStreamNonBlocking);
    cudaEventCreateWithFlags(&ev0, cudaEventDisableTiming);
    cudaEventCreateWithFlags(&evE, cudaEventDisableTiming);
    for (int i = 0; i < LAYERS; i++) {
        cudaEventCreateWithFlags(&evA[i], cudaEventDisableTiming);
        cudaEventCreateWithFlags(&evB[i], cudaEventDisableTiming);
        cudaEventCreateWithFlags(&evK[i], cudaEventDisableTiming);
        cudaEventCreateWithFlags(&evX[i], cudaEventDisableTiming);
        cudaEventCreateWithFlags(&evR[i], cudaEventDisableTiming);
    }
    cudaFuncSetAttribute(h16_gemm<0>, cudaFuncAttributeMaxDynamicSharedMemorySize, GEMM_SMEM_BYTES);
    cudaFuncSetAttribute(h16_gemm<1>, cudaFuncAttributeMaxDynamicSharedMemorySize, GEMM_SMEM_BYTES);
    cudaFuncSetAttribute(attn_tile_kernel, cudaFuncAttributeMaxDynamicSharedMemorySize, ATTN_SMEM);
    g_inited = true;
}

extern "C" void kernel_launch(void* const* d_in, const int* in_sizes, int n_in,
                              void* d_out, int out_size) {
    init_once();
    cudaStream_t s0 = 0;

    const float* vlm_embeds    = (const float*)d_in[0];
    const float* expert_embeds = (const float*)d_in[1];
    const float* w_vlm_q       = (const float*)d_in[2];
    const float* w_vlm_k       = (const float*)d_in[3];
    const float* w_vlm_v       = (const float*)d_in[4];
    const float* w_vlm_o       = (const float*)d_in[5];
    const float* w_vlm_ln1     = (const float*)d_in[6];
    const float* w_vlm_ln2     = (const float*)d_in[7];
    const float* w_vlm_gate    = (const float*)d_in[8];
    const float* w_vlm_up      = (const float*)d_in[9];
    const float* w_vlm_down    = (const float*)d_in[10];
    const float* w_vlm_fnorm   = (const float*)d_in[11];
    const float* w_exp_q       = (const float*)d_in[12];
    const float* w_exp_k_self  = (const float*)d_in[13];
    const float* w_exp_v_self  = (const float*)d_in[14];
    const float* w_exp_k_cross = (const float*)d_in[15];
    const float* w_exp_v_cross = (const float*)d_in[16];
    const float* w_exp_o       = (const float*)d_in[17];
    const float* w_exp_ln1     = (const float*)d_in[18];
    const float* w_exp_ln2     = (const float*)d_in[19];
    const float* w_exp_gate    = (const float*)d_in[20];
    const float* w_exp_up      = (const float*)d_in[21];
    const float* w_exp_down    = (const float*)d_in[22];
    const float* w_exp_fnorm   = (const float*)d_in[23];

    float* vlm = sym(g_vlm);
    float* exq = sym(g_exp);
    float* hv  = sym(g_hv);
    float* he  = sym(g_he);
    float* q   = sym(g_q);
    float* k   = sym(g_k);
    float* v   = sym(g_v);
    float* ke  = sym(g_ke);
    float* ve  = sym(g_ve);
    float* att = sym(g_att);
    float* gg  = sym(g_g);
    float* gu  = sym(g_u);
    float* gge = sym(g_ge);
    float* gue = sym(g_ue);
    float* p0  = sym(g_p0);
    float* p2  = sym(g_p2);

    cudaMemcpyAsync(vlm, vlm_embeds,    (size_t)PL * TH * sizeof(float),
                    cudaMemcpyDeviceToDevice, s0);
    cudaMemcpyAsync(exq, expert_embeds, (size_t)EL * EH * sizeof(float),
                    cudaMemcpyDeviceToDevice, s0);
    cudaEventRecord(ev0, s0);
    cudaStreamWaitEvent(s2, ev0, 0);

    for (int li = 0; li < LAYERS; li++) {
        if ((li & 1) == 0) {
            // ======== EVEN: joint attention over S=640 ========
            rmsnorm_kernel<<<EL, 256, 0, s2>>>(exq, w_exp_ln1 + (size_t)li * EH, he, EH);
            {
                GemmSegs gs = {};
                gs.s[0] = mkseg(he, w_exp_q      + (size_t)li * EH * (NH * HD),        q + PL * NH * HD,  NH * HD);
                gs.s[1] = mkseg(he, w_exp_k_self + (size_t)(li / 2) * EH * (NKV * HD), k + PL * NKV * HD, NKV * HD);
                gs.s[2] = mkseg(he, w_exp_v_self + (size_t)(li / 2) * EH * (NKV * HD), v + PL * NKV * HD, NKV * HD);
                gemmN(gs, 3, EL, EH, false, s2);
            }
            cudaEventRecord(evA[li], s2);

            if (li > 0) cudaStreamWaitEvent(s0, evX[li - 1], 0);
            rmsnorm_kernel<<<PL, 256, 0, s0>>>(vlm, w_vlm_ln1 + (size_t)li * TH, hv, TH);
            {
                GemmSegs gs = {};
                gs.s[0] = mkseg(hv, w_vlm_q + (size_t)li * TH * (NH * HD),  q, NH * HD);
                gs.s[1] = mkseg(hv, w_vlm_k + (size_t)li * TH * (NKV * HD), k, NKV * HD);
                gs.s[2] = mkseg(hv, w_vlm_v + (size_t)li * TH * (NKV * HD), v, NKV * HD);
                gemmN(gs, 3, PL, TH, false, s0);
            }

            cudaStreamWaitEvent(s0, evA[li], 0);
            {
                int t = SS * NH * 32 + SS * NKV * 32;
                rope_qk_kernel<<<(t + 255) / 256, 256, 0, s0>>>(q, SS, k, SS);
            }
            if (li > 0) cudaStreamWaitEvent(s0, evR[li - 1], 0);
            attn_tile_kernel<<<dim3(SS / 64, NH), 256, ATTN_SMEM, s0>>>(q, k, v, att, SS, PL);
            cudaEventRecord(evB[li], s0);

            cudaStreamWaitEvent(s2, evB[li], 0);
            gemmSplit(att + PL * NH * HD, w_exp_o + (size_t)li * (NH * HD) * EH,
                      exq, p2, EL, EH, NH * HD, s2);
            rmsnorm_kernel<<<EL, 256, 0, s2>>>(exq, w_exp_ln2 + (size_t)li * EH, he, EH);
            {
                GemmSegs gs = {};
                gs.s[0] = mkseg(he, w_exp_gate + (size_t)li * EH * EI, gge, EI);
                gs.s[1] = mkseg(he, w_exp_up   + (size_t)li * EH * EI, gue, EI);
                gemmN(gs, 2, EL, EH, false, s2);
            }
            silu_mul_kernel<<<(EL * EI + 255) / 256, 256, 0, s2>>>(gge, gue, gge, EL * EI);
            gemmSplit(gge, w_exp_down + (size_t)li * EI * EH, exq, p2, EL, EH, EI, s2);

            gemmSplit(att, w_vlm_o + (size_t)li * (NH * HD) * TH, vlm, p0,
                      PL, TH, NH * HD, s0);
            rmsnorm_kernel<<<PL, 256, 0, s0>>>(vlm, w_vlm_ln2 + (size_t)li * TH, hv, TH);
            {
                GemmSegs gs = {};
                gs.s[0] = mkseg(hv, w_vlm_gate + (size_t)li * TH * TI, gg, TI);
                gs.s[1] = mkseg(hv, w_vlm_up   + (size_t)li * TH * TI, gu, TI);
                gemmN(gs, 2, PL, TH, false, s0);
            }
            silu_mul_kernel<<<(PL * TI + 255) / 256, 256, 0, s0>>>(gg, gu, gg, PL * TI);
            gemmSplit(gg, w_vlm_down + (size_t)li * TI * TH, vlm, p0, PL, TH, TI, s0);
        } else {
            // ======== ODD: vlm self-attn + expert cross-attn ========
            rmsnorm_kernel<<<PL, 256, 0, s0>>>(vlm, w_vlm_ln1 + (size_t)li * TH, hv, TH);
            {
                GemmSegs gs = {};
                gs.s[0] = mkseg(hv, w_vlm_q + (size_t)li * TH * (NH * HD),  q, NH * HD);
                gs.s[1] = mkseg(hv, w_vlm_k + (size_t)li * TH * (NKV * HD), k, NKV * HD);
                gs.s[2] = mkseg(hv, w_vlm_v + (size_t)li * TH * (NKV * HD), v, NKV * HD);
                gemmN(gs, 3, PL, TH, false, s0);
            }
            {
                int t = PL * NH * 32 + PL * NKV * 32;
                rope_qk_kernel<<<(t + 255) / 256, 256, 0, s0>>>(q, PL, k, PL);
            }
            cudaEventRecord(evK[li], s0);

            rmsnorm_kernel<<<EL, 256, 0, s2>>>(exq, w_exp_ln1 + (size_t)li * EH, he, EH);
            gemm1(he, w_exp_q + (size_t)li * EH * (NH * HD), q + PL * NH * HD,
                  EL, NH * HD, EH, false, s2);
            { int t = EL * NH * 32; rope_kernel<<<(t + 255) / 256, 256, 0, s2>>>(q + PL * NH * HD, EL, NH, PL); }
            cudaStreamWaitEvent(s2, evK[li], 0);
            {
                GemmSegs gs = {};
                gs.s[0] = mkseg(k, w_exp_k_cross + (size_t)(li / 2) * (NKV * HD) * (NKV * HD), ke, NKV * HD);
                gs.s[1] = mkseg(v, w_exp_v_cross + (size_t)(li / 2) * (NKV * HD) * (NKV * HD), ve, NKV * HD);
                gemmN(gs, 2, PL, NKV * HD, false, s2);
            }
            cudaEventRecord(evX[li], s2);
            attn_tile_kernel<<<dim3(EL / 64, NH), 256, ATTN_SMEM, s2>>>(
                q + PL * NH * HD, ke, ve, att + PL * NH * HD, PL, 0);
            gemmSplit(att + PL * NH * HD, w_exp_o + (size_t)li * (NH * HD) * EH,
                      exq, p2, EL, EH, NH * HD, s2);
            cudaEventRecord(evR[li], s2);
            rmsnorm_kernel<<<EL, 256, 0, s2>>>(exq, w_exp_ln2 + (size_t)li * EH, he, EH);
            {
                GemmSegs gs = {};
                gs.s[0] = mkseg(he, w_exp_gate + (size_t)li * EH * EI, gge, EI);
                gs.s[1] = mkseg(he, w_exp_up   + (size_t)li * EH * EI, gue, EI);
                gemmN(gs, 2, EL, EH, false, s2);
            }
            silu_mul_kernel<<<(EL * EI + 255) / 256, 256, 0, s2>>>(gge, gue, gge, EL * EI);
            gemmSplit(gge, w_exp_down + (size_t)li * EI * EH, exq, p2, EL, EH, EI, s2);
            if (li == LAYERS - 1) cudaEventRecord(evE, s2);

            attn_tile_kernel<<<dim3(PL / 64, NH), 256, ATTN_SMEM, s0>>>(q, k, v, att, PL, 0);
            gemmSplit(att, w_vlm_o + (size_t)li * (NH * HD) * TH, vlm, p0,
                      PL, TH, NH * HD, s0);
            rmsnorm_kernel<<<PL, 256, 0, s0>>>(vlm, w_vlm_ln2 + (size_t)li * TH, hv, TH);
            {
                GemmSegs gs = {};
                gs.s[0] = mkseg(hv, w_vlm_gate + (size_t)li * TH * TI, gg, TI);
                gs.s[1] = mkseg(hv, w_vlm_up   + (size_t)li * TH * TI, gu, TI);
                gemmN(gs, 2, PL, TH, false, s0);
            }
            silu_mul_kernel<<<(PL * TI + 255) / 256, 256, 0, s0>>>(gg, gu, gg, PL * TI);
            gemmSplit(gg, w_vlm_down + (size_t)li * TI * TH, vlm, p0, PL, TH, TI, s0);
        }
    }

    cudaStreamWaitEvent(s0, evE, 0);
    float* out = (float*)d_out;
    rmsnorm_kernel<<<PL, 256, 0, s0>>>(vlm, w_vlm_fnorm, out, TH);
    rmsnorm_kernel<<<EL, 256, 0, s0>>>(exq, w_exp_fnorm, out + (size_t)PL * TH, EH);
}